// round 2
// baseline (speedup 1.0000x reference)
#include <cuda_runtime.h>
#include <math.h>

// Problem constants
#define DMODEL 768
#define NTOK   2048          // B*N = 2*1024
#define NSEQ   1024
#define NHEAD  12
#define HDIM   64
#define NLAYER 12
#define NVOCAB 50257

// ---------------------------------------------------------------------------
// Device-global scratch (allocation-free; harness forbids cudaMalloc)
// ---------------------------------------------------------------------------
__device__ float g_x[NTOK * DMODEL];             // residual stream
__device__ float g_ln[NTOK * DMODEL];            // layernorm output
__device__ float g_qkv[NTOK * 3 * DMODEL];       // qkv projections
__device__ float g_attn[NTOK * DMODEL];          // attention output (B,N,D)
__device__ float g_mid[NTOK * 4 * DMODEL];       // MLP hidden
__device__ float g_scores[2 * NHEAD * NSEQ * NSEQ]; // attention scores/probs (~100MB)

// ---------------------------------------------------------------------------
// Block reduction helpers (blockDim.x == 256)
// ---------------------------------------------------------------------------
__device__ __forceinline__ float blockReduceSum(float v) {
    __shared__ float sh[8];
    int lane = threadIdx.x & 31, w = threadIdx.x >> 5;
#pragma unroll
    for (int o = 16; o; o >>= 1) v += __shfl_xor_sync(0xffffffffu, v, o);
    __syncthreads();                 // protect sh reuse across calls
    if (lane == 0) sh[w] = v;
    __syncthreads();
    if (threadIdx.x == 0) {
        float s = sh[0];
#pragma unroll
        for (int i = 1; i < 8; i++) s += sh[i];
        sh[0] = s;
    }
    __syncthreads();
    return sh[0];
}

__device__ __forceinline__ float blockReduceMax(float v) {
    __shared__ float sh[8];
    int lane = threadIdx.x & 31, w = threadIdx.x >> 5;
#pragma unroll
    for (int o = 16; o; o >>= 1) v = fmaxf(v, __shfl_xor_sync(0xffffffffu, v, o));
    __syncthreads();
    if (lane == 0) sh[w] = v;
    __syncthreads();
    if (threadIdx.x == 0) {
        float s = sh[0];
#pragma unroll
        for (int i = 1; i < 8; i++) s = fmaxf(s, sh[i]);
        sh[0] = s;
    }
    __syncthreads();
    return sh[0];
}

// ---------------------------------------------------------------------------
// Embedding: x[t] = wte[token[t]] + wpe[t % NSEQ]
// ---------------------------------------------------------------------------
__global__ void embed_kernel(const int* __restrict__ tok,
                             const float* __restrict__ wte,
                             const float* __restrict__ wpe,
                             float* __restrict__ x) {
    int t = blockIdx.x;
    int n = t & (NSEQ - 1);
    int id = tok[t];
    const float* w1 = wte + (long)id * DMODEL;
    const float* w2 = wpe + (long)n * DMODEL;
    float* xo = x + (long)t * DMODEL;
    for (int d = threadIdx.x; d < DMODEL; d += blockDim.x)
        xo[d] = w1[d] + w2[d];
}

// ---------------------------------------------------------------------------
// LayerNorm (row per block, 256 threads; D = 768 = 3*256)
// ---------------------------------------------------------------------------
__global__ __launch_bounds__(256) void layernorm_kernel(
    const float* __restrict__ x, const float* __restrict__ w,
    const float* __restrict__ b, float* __restrict__ out) {
    int t = blockIdx.x;
    const float* xr = x + (long)t * DMODEL;
    float* o = out + (long)t * DMODEL;
    int tid = threadIdx.x;

    float lx[3];
    float s = 0.f;
#pragma unroll
    for (int i = 0; i < 3; i++) { lx[i] = xr[tid + i * 256]; s += lx[i]; }
    s = blockReduceSum(s);
    float mu = s * (1.f / 768.f);

    float var = 0.f;
#pragma unroll
    for (int i = 0; i < 3; i++) { float d = lx[i] - mu; var += d * d; }
    var = blockReduceSum(var);
    float rstd = rsqrtf(var * (1.f / 768.f) + 1e-5f);

#pragma unroll
    for (int i = 0; i < 3; i++) {
        int d = tid + i * 256;
        o[d] = (lx[i] - mu) * rstd * w[d] + b[d];
    }
}

// ---------------------------------------------------------------------------
// Causal softmax over scores rows. scale = 1/sqrt(64) = 0.125.
// Writes exact zeros for k > q so the PV GEMM can run over full K.
// ---------------------------------------------------------------------------
__global__ __launch_bounds__(256) void softmax_kernel(float* __restrict__ scores) {
    int q = blockIdx.x, z = blockIdx.y;
    float* row = scores + (long)z * NSEQ * NSEQ + (long)q * NSEQ;
    int tid = threadIdx.x;
    const float scale = 0.125f;

    float mx = -1e30f;
    for (int k = tid; k <= q; k += 256) mx = fmaxf(mx, row[k] * scale);
    mx = blockReduceMax(mx);

    float sum = 0.f;
    for (int k = tid; k <= q; k += 256) {
        float e = expf(row[k] * scale - mx);
        row[k] = e;
        sum += e;
    }
    sum = blockReduceSum(sum);
    float inv = 1.f / sum;

    for (int k = tid; k <= q; k += 256) row[k] *= inv;
    for (int k = q + 1 + tid; k < NSEQ; k += 256) row[k] = 0.f;
}

// ---------------------------------------------------------------------------
// Generic tiled GEMM: C = A @ B (+bias)(+residual)(gelu)
//   64x64 tile, BK=16, 256 threads, 4x4 accum per thread.
//   TB: B stored [N,K] row-major (dot over rows of both A and B).
//   2-level batch: z -> (z/Z2, z%Z2) with independent strides per operand.
//   flags: 1=residual (C += result), 2=exact GELU, 4=causal tile skip.
//   Assumes M % 64 == 0 and K % 16 == 0 (true for all uses here); N guarded.
// ---------------------------------------------------------------------------
template<bool TB>
__global__ __launch_bounds__(256) void gemm_kernel(
    const float* __restrict__ A, int lda, long sA1, long sA2,
    const float* __restrict__ B, int ldb, long sB1, long sB2,
    float* __restrict__ C, int ldc, long sC1, long sC2,
    const float* __restrict__ bias,
    int M, int N, int K, int Z2, int flags) {

    int m0 = blockIdx.y * 64, n0 = blockIdx.x * 64;
    if ((flags & 4) && n0 > m0 + 63) return;   // fully-masked causal tile

    int z = blockIdx.z;
    int z1 = z / Z2, z2 = z % Z2;
    A += (long)z1 * sA1 + (long)z2 * sA2;
    B += (long)z1 * sB1 + (long)z2 * sB2;
    C += (long)z1 * sC1 + (long)z2 * sC2;

    __shared__ float As[16][64];
    __shared__ float Bs[16][64];

    int tid = threadIdx.x;
    int tx = tid & 15, ty = tid >> 4;
    float acc[4][4] = {};

    for (int k0 = 0; k0 < K; k0 += 16) {
#pragma unroll
        for (int i = 0; i < 4; i++) {
            int idx = tid + i * 256;
            int m = idx >> 4, k = idx & 15;
            As[k][m] = A[(long)(m0 + m) * lda + (k0 + k)];
        }
#pragma unroll
        for (int i = 0; i < 4; i++) {
            int idx = tid + i * 256;
            if (TB) {
                int n = idx >> 4, k = idx & 15;
                int gn = n0 + n;
                Bs[k][n] = (gn < N) ? B[(long)gn * ldb + (k0 + k)] : 0.f;
            } else {
                int k = idx >> 6, n = idx & 63;
                int gn = n0 + n;
                Bs[k][n] = (gn < N) ? B[(long)(k0 + k) * ldb + gn] : 0.f;
            }
        }
        __syncthreads();
#pragma unroll
        for (int k = 0; k < 16; k++) {
            float4 a4 = *(const float4*)&As[k][ty * 4];
            float4 b4 = *(const float4*)&Bs[k][tx * 4];
            float ra[4] = {a4.x, a4.y, a4.z, a4.w};
            float rb[4] = {b4.x, b4.y, b4.z, b4.w};
#pragma unroll
            for (int i = 0; i < 4; i++)
#pragma unroll
                for (int j = 0; j < 4; j++)
                    acc[i][j] = fmaf(ra[i], rb[j], acc[i][j]);
        }
        __syncthreads();
    }

#pragma unroll
    for (int i = 0; i < 4; i++) {
        int gm = m0 + ty * 4 + i;
#pragma unroll
        for (int j = 0; j < 4; j++) {
            int gn = n0 + tx * 4 + j;
            if (gn < N) {
                float v = acc[i][j];
                if (bias) v += bias[gn];
                if (flags & 2) v = 0.5f * v * (1.f + erff(v * 0.70710678118654752f));
                float* p = &C[(long)gm * ldc + gn];
                if (flags & 1) v += *p;
                *p = v;
            }
        }
    }
}

// ---------------------------------------------------------------------------
// Host-side orchestration
// ---------------------------------------------------------------------------
extern "C" void kernel_launch(void* const* d_in, const int* in_sizes, int n_in,
                              void* d_out, int out_size) {
    (void)in_sizes; (void)n_in; (void)out_size;

    const int*   tok     = (const int*)  d_in[0];
    const float* wte     = (const float*)d_in[1];
    const float* wpe     = (const float*)d_in[2];
    const float* ln1_w   = (const float*)d_in[3];
    const float* ln1_b   = (const float*)d_in[4];
    const float* attn_w  = (const float*)d_in[5];
    const float* attn_b  = (const float*)d_in[6];
    const float* aproj_w = (const float*)d_in[7];
    const float* aproj_b = (const float*)d_in[8];
    const float* ln2_w   = (const float*)d_in[9];
    const float* ln2_b   = (const float*)d_in[10];
    const float* fc_w    = (const float*)d_in[11];
    const float* fc_b    = (const float*)d_in[12];
    const float* mproj_w = (const float*)d_in[13];
    const float* mproj_b = (const float*)d_in[14];
    const float* lnf_w   = (const float*)d_in[15];
    const float* lnf_b   = (const float*)d_in[16];
    float* out = (float*)d_out;

    float *x, *ln, *qkv, *attn, *mid, *scores;
    cudaGetSymbolAddress((void**)&x,      g_x);
    cudaGetSymbolAddress((void**)&ln,     g_ln);
    cudaGetSymbolAddress((void**)&qkv,    g_qkv);
    cudaGetSymbolAddress((void**)&attn,   g_attn);
    cudaGetSymbolAddress((void**)&mid,    g_mid);
    cudaGetSymbolAddress((void**)&scores, g_scores);

    const int D = DMODEL;

    embed_kernel<<<NTOK, 256>>>(tok, wte, wpe, x);

    for (int l = 0; l < NLAYER; l++) {
        // h = LN1(x)
        layernorm_kernel<<<NTOK, 256>>>(x, ln1_w + l * D, ln1_b + l * D, ln);

        // qkv = h @ attn_w[l] + attn_b[l]   [2048, 2304]
        {
            dim3 g(3 * D / 64, NTOK / 64);
            gemm_kernel<false><<<g, 256>>>(
                ln, D, 0, 0,
                attn_w + (long)l * D * 3 * D, 3 * D, 0, 0,
                qkv, 3 * D, 0, 0,
                attn_b + (long)l * 3 * D,
                NTOK, 3 * D, D, 1, 0);
        }

        // scores[z] = Q_z @ K_z^T  (z = b*12 + h); masked tiles skipped
        {
            dim3 g(NSEQ / 64, NSEQ / 64, 2 * NHEAD);
            gemm_kernel<true><<<g, 256>>>(
                qkv,     3 * D, (long)NSEQ * 3 * D, HDIM,   // Q
                qkv + D, 3 * D, (long)NSEQ * 3 * D, HDIM,   // K
                scores, NSEQ, (long)NHEAD * NSEQ * NSEQ, (long)NSEQ * NSEQ,
                nullptr,
                NSEQ, NSEQ, HDIM, NHEAD, 4);
        }

        // causal softmax (applies 1/sqrt(64) scale, zero-fills masked region)
        softmax_kernel<<<dim3(NSEQ, 2 * NHEAD), 256>>>(scores);

        // attn[z] = P_z @ V_z  -> written into (B,N,D) layout at head offset
        {
            dim3 g(1, NSEQ / 64, 2 * NHEAD);
            gemm_kernel<false><<<g, 256>>>(
                scores, NSEQ, (long)NHEAD * NSEQ * NSEQ, (long)NSEQ * NSEQ,
                qkv + 2 * D, 3 * D, (long)NSEQ * 3 * D, HDIM,  // V
                attn, D, (long)NSEQ * D, HDIM,
                nullptr,
                NSEQ, HDIM, NSEQ, NHEAD, 0);
        }

        // x += attn @ aproj_w[l] + aproj_b[l]
        {
            dim3 g(D / 64, NTOK / 64);
            gemm_kernel<false><<<g, 256>>>(
                attn, D, 0, 0,
                aproj_w + (long)l * D * D, D, 0, 0,
                x, D, 0, 0,
                aproj_b + (long)l * D,
                NTOK, D, D, 1, 1);
        }

        // h = LN2(x)
        layernorm_kernel<<<NTOK, 256>>>(x, ln2_w + l * D, ln2_b + l * D, ln);

        // mid = gelu(h @ fc_w[l] + fc_b[l])   [2048, 3072]
        {
            dim3 g(4 * D / 64, NTOK / 64);
            gemm_kernel<false><<<g, 256>>>(
                ln, D, 0, 0,
                fc_w + (long)l * D * 4 * D, 4 * D, 0, 0,
                mid, 4 * D, 0, 0,
                fc_b + (long)l * 4 * D,
                NTOK, 4 * D, D, 1, 2);
        }

        // x += mid @ mproj_w[l] + mproj_b[l]
        {
            dim3 g(D / 64, NTOK / 64);
            gemm_kernel<false><<<g, 256>>>(
                mid, 4 * D, 0, 0,
                mproj_w + (long)l * 4 * D * D, D, 0, 0,
                x, D, 0, 0,
                mproj_b + (long)l * D,
                NTOK, D, 4 * D, 1, 1);
        }
    }

    // final LN + tied lm_head: out = LN_f(x) @ wte^T   [2048, 50257]
    layernorm_kernel<<<NTOK, 256>>>(x, lnf_w, lnf_b, ln);
    {
        dim3 g((NVOCAB + 63) / 64, NTOK / 64);
        gemm_kernel<true><<<g, 256>>>(
            ln, D, 0, 0,
            wte, D, 0, 0,
            out, NVOCAB, 0, 0,
            nullptr,
            NTOK, NVOCAB, D, 1, 0);
    }
}

// round 3
// speedup vs baseline: 1.4319x; 1.4319x over previous
#include <cuda_runtime.h>
#include <math.h>

// Problem constants
#define DMODEL 768
#define NTOK   2048          // B*N = 2*1024
#define NSEQ   1024
#define NHEAD  12
#define HDIM   64
#define NLAYER 12
#define NVOCAB 50257

// ---------------------------------------------------------------------------
// Device-global scratch (allocation-free; harness forbids cudaMalloc)
// ---------------------------------------------------------------------------
__device__ float g_x[NTOK * DMODEL];             // residual stream
__device__ float g_ln[NTOK * DMODEL];            // layernorm output
__device__ float g_qkv[NTOK * 3 * DMODEL];       // qkv projections
__device__ float g_attn[NTOK * DMODEL];          // attention output (B,N,D)
__device__ float g_mid[NTOK * 4 * DMODEL];       // MLP hidden
__device__ float g_scores[2 * NHEAD * NSEQ * NSEQ]; // attention scores/probs (~100MB)

// ---------------------------------------------------------------------------
// Block reduction helpers (blockDim.x == 256)
// ---------------------------------------------------------------------------
__device__ __forceinline__ float blockReduceSum(float v) {
    __shared__ float sh[8];
    int lane = threadIdx.x & 31, w = threadIdx.x >> 5;
#pragma unroll
    for (int o = 16; o; o >>= 1) v += __shfl_xor_sync(0xffffffffu, v, o);
    __syncthreads();
    if (lane == 0) sh[w] = v;
    __syncthreads();
    if (threadIdx.x == 0) {
        float s = sh[0];
#pragma unroll
        for (int i = 1; i < 8; i++) s += sh[i];
        sh[0] = s;
    }
    __syncthreads();
    return sh[0];
}

__device__ __forceinline__ float blockReduceMax(float v) {
    __shared__ float sh[8];
    int lane = threadIdx.x & 31, w = threadIdx.x >> 5;
#pragma unroll
    for (int o = 16; o; o >>= 1) v = fmaxf(v, __shfl_xor_sync(0xffffffffu, v, o));
    __syncthreads();
    if (lane == 0) sh[w] = v;
    __syncthreads();
    if (threadIdx.x == 0) {
        float s = sh[0];
#pragma unroll
        for (int i = 1; i < 8; i++) s = fmaxf(s, sh[i]);
        sh[0] = s;
    }
    __syncthreads();
    return sh[0];
}

// ---------------------------------------------------------------------------
// Embedding: x[t] = wte[token[t]] + wpe[t % NSEQ]
// ---------------------------------------------------------------------------
__global__ void embed_kernel(const int* __restrict__ tok,
                             const float* __restrict__ wte,
                             const float* __restrict__ wpe,
                             float* __restrict__ x) {
    int t = blockIdx.x;
    int n = t & (NSEQ - 1);
    int id = tok[t];
    const float* w1 = wte + (long)id * DMODEL;
    const float* w2 = wpe + (long)n * DMODEL;
    float* xo = x + (long)t * DMODEL;
    for (int d = threadIdx.x; d < DMODEL; d += blockDim.x)
        xo[d] = w1[d] + w2[d];
}

// ---------------------------------------------------------------------------
// LayerNorm (row per block, 256 threads; D = 768 = 3*256)
// ---------------------------------------------------------------------------
__global__ __launch_bounds__(256) void layernorm_kernel(
    const float* __restrict__ x, const float* __restrict__ w,
    const float* __restrict__ b, float* __restrict__ out) {
    int t = blockIdx.x;
    const float* xr = x + (long)t * DMODEL;
    float* o = out + (long)t * DMODEL;
    int tid = threadIdx.x;

    float lx[3];
    float s = 0.f;
#pragma unroll
    for (int i = 0; i < 3; i++) { lx[i] = xr[tid + i * 256]; s += lx[i]; }
    s = blockReduceSum(s);
    float mu = s * (1.f / 768.f);

    float var = 0.f;
#pragma unroll
    for (int i = 0; i < 3; i++) { float d = lx[i] - mu; var += d * d; }
    var = blockReduceSum(var);
    float rstd = rsqrtf(var * (1.f / 768.f) + 1e-5f);

#pragma unroll
    for (int i = 0; i < 3; i++) {
        int d = tid + i * 256;
        o[d] = (lx[i] - mu) * rstd * w[d] + b[d];
    }
}

// ---------------------------------------------------------------------------
// Causal softmax over scores rows. scale = 1/sqrt(64) = 0.125.
// Writes exact zeros for k > q so the PV GEMM can truncate K exactly.
// ---------------------------------------------------------------------------
__global__ __launch_bounds__(256) void softmax_kernel(float* __restrict__ scores) {
    int q = blockIdx.x, z = blockIdx.y;
    float* row = scores + (long)z * NSEQ * NSEQ + (long)q * NSEQ;
    int tid = threadIdx.x;
    const float scale = 0.125f;

    float mx = -1e30f;
    for (int k = tid; k <= q; k += 256) mx = fmaxf(mx, row[k] * scale);
    mx = blockReduceMax(mx);

    float sum = 0.f;
    for (int k = tid; k <= q; k += 256) {
        float e = expf(row[k] * scale - mx);
        row[k] = e;
        sum += e;
    }
    sum = blockReduceSum(sum);
    float inv = 1.f / sum;

    for (int k = tid; k <= q; k += 256) row[k] *= inv;
    for (int k = q + 1 + tid; k < NSEQ; k += 256) row[k] = 0.f;
}

// ---------------------------------------------------------------------------
// Big GEMM: 128x128 tile, BK=8, 256 threads, 8x8 microtile, double-buffered.
//   C = A @ B (+bias)(+residual)(gelu)
//   TB: B stored [N,K] row-major. flags: 1=residual, 2=gelu, 4=causal skip.
//   Requirements: M%128==0, K%8==0 (true for all uses). N guarded (TB path).
//   Non-TB callers all have N%128==0 (no N guard on loads there).
// ---------------------------------------------------------------------------
template<bool TB>
__global__ __launch_bounds__(256, 2) void gemm128_kernel(
    const float* __restrict__ A, int lda, long sA1, long sA2,
    const float* __restrict__ B, int ldb, long sB1, long sB2,
    float* __restrict__ C, int ldc, long sC1, long sC2,
    const float* __restrict__ bias,
    int M, int N, int K, int Z2, int flags) {

    int m0 = blockIdx.y * 128, n0 = blockIdx.x * 128;
    if ((flags & 4) && n0 > m0 + 127) return;   // fully-masked causal tile

    int z = blockIdx.z;
    int z1 = z / Z2, z2 = z % Z2;
    A += (long)z1 * sA1 + (long)z2 * sA2;
    B += (long)z1 * sB1 + (long)z2 * sB2;
    C += (long)z1 * sC1 + (long)z2 * sC2;

    __shared__ float As[2][8][128];
    __shared__ float Bs[2][8][128];

    int tid = threadIdx.x;
    // A tile load: thread -> (row = tid>>1 in 0..127, kcol = (tid&1)*4), one float4
    int arow = tid >> 1, acol = (tid & 1) * 4;
    // B tile load
    int brow, bcol;
    if (TB) { brow = tid >> 1; bcol = (tid & 1) * 4; }   // row n in [N,K]
    else    { brow = tid >> 5; bcol = (tid & 31) * 4; }  // row k, col n

    int tx = tid & 15, ty = tid >> 4;
    float acc[8][8] = {};
    float4 a_reg, b_reg;

    auto ldG = [&](int k0) {
        a_reg = *(const float4*)&A[(long)(m0 + arow) * lda + (k0 + acol)];
        if (TB) {
            int gn = n0 + brow;
            if (gn < N) b_reg = *(const float4*)&B[(long)gn * ldb + (k0 + bcol)];
            else        b_reg = make_float4(0.f, 0.f, 0.f, 0.f);
        } else {
            b_reg = *(const float4*)&B[(long)(k0 + brow) * ldb + (n0 + bcol)];
        }
    };
    auto stS = [&](int buf) {
        As[buf][acol + 0][arow] = a_reg.x;
        As[buf][acol + 1][arow] = a_reg.y;
        As[buf][acol + 2][arow] = a_reg.z;
        As[buf][acol + 3][arow] = a_reg.w;
        if (TB) {
            Bs[buf][bcol + 0][brow] = b_reg.x;
            Bs[buf][bcol + 1][brow] = b_reg.y;
            Bs[buf][bcol + 2][brow] = b_reg.z;
            Bs[buf][bcol + 3][brow] = b_reg.w;
        } else {
            *(float4*)&Bs[buf][brow][bcol] = b_reg;
        }
    };

    ldG(0);
    stS(0);
    __syncthreads();

    int KT = K >> 3;
    int buf = 0;
    for (int kt = 0; kt < KT; kt++) {
        if (kt + 1 < KT) ldG((kt + 1) << 3);
#pragma unroll
        for (int k = 0; k < 8; k++) {
            float4 a0 = *(const float4*)&As[buf][k][ty * 8];
            float4 a1 = *(const float4*)&As[buf][k][ty * 8 + 4];
            float4 b0 = *(const float4*)&Bs[buf][k][tx * 8];
            float4 b1 = *(const float4*)&Bs[buf][k][tx * 8 + 4];
            float ra[8] = {a0.x, a0.y, a0.z, a0.w, a1.x, a1.y, a1.z, a1.w};
            float rb[8] = {b0.x, b0.y, b0.z, b0.w, b1.x, b1.y, b1.z, b1.w};
#pragma unroll
            for (int i = 0; i < 8; i++)
#pragma unroll
                for (int j = 0; j < 8; j++)
                    acc[i][j] = fmaf(ra[i], rb[j], acc[i][j]);
        }
        if (kt + 1 < KT) {
            stS(buf ^ 1);
            __syncthreads();
            buf ^= 1;
        }
    }

#pragma unroll
    for (int i = 0; i < 8; i++) {
        int gm = m0 + ty * 8 + i;
#pragma unroll
        for (int j = 0; j < 8; j++) {
            int gn = n0 + tx * 8 + j;
            if (gn < N) {
                float v = acc[i][j];
                if (bias) v += bias[gn];
                if (flags & 2) v = 0.5f * v * (1.f + erff(v * 0.70710678118654752f));
                float* p = &C[(long)gm * ldc + gn];
                if (flags & 1) v += *p;
                *p = v;
            }
        }
    }
}

// ---------------------------------------------------------------------------
// Small GEMM (64x64 tile, BK=16) retained for PV (N=64).
//   flags: 8 = causal K truncation (K_eff = min(K, m0+64)); softmax zero-fill
//   makes this exact.
// ---------------------------------------------------------------------------
__global__ __launch_bounds__(256) void gemm64_kernel(
    const float* __restrict__ A, int lda, long sA1, long sA2,
    const float* __restrict__ B, int ldb, long sB1, long sB2,
    float* __restrict__ C, int ldc, long sC1, long sC2,
    const float* __restrict__ bias,
    int M, int N, int K, int Z2, int flags) {

    int m0 = blockIdx.y * 64, n0 = blockIdx.x * 64;

    int z = blockIdx.z;
    int z1 = z / Z2, z2 = z % Z2;
    A += (long)z1 * sA1 + (long)z2 * sA2;
    B += (long)z1 * sB1 + (long)z2 * sB2;
    C += (long)z1 * sC1 + (long)z2 * sC2;

    __shared__ float As[16][64];
    __shared__ float Bs[16][64];

    int tid = threadIdx.x;
    int tx = tid & 15, ty = tid >> 4;
    float acc[4][4] = {};

    int Kend = (flags & 8) ? min(K, m0 + 64) : K;

    for (int k0 = 0; k0 < Kend; k0 += 16) {
#pragma unroll
        for (int i = 0; i < 4; i++) {
            int idx = tid + i * 256;
            int m = idx >> 4, k = idx & 15;
            As[k][m] = A[(long)(m0 + m) * lda + (k0 + k)];
        }
#pragma unroll
        for (int i = 0; i < 4; i++) {
            int idx = tid + i * 256;
            int k = idx >> 6, n = idx & 63;
            int gn = n0 + n;
            Bs[k][n] = (gn < N) ? B[(long)(k0 + k) * ldb + gn] : 0.f;
        }
        __syncthreads();
#pragma unroll
        for (int k = 0; k < 16; k++) {
            float4 a4 = *(const float4*)&As[k][ty * 4];
            float4 b4 = *(const float4*)&Bs[k][tx * 4];
            float ra[4] = {a4.x, a4.y, a4.z, a4.w};
            float rb[4] = {b4.x, b4.y, b4.z, b4.w};
#pragma unroll
            for (int i = 0; i < 4; i++)
#pragma unroll
                for (int j = 0; j < 4; j++)
                    acc[i][j] = fmaf(ra[i], rb[j], acc[i][j]);
        }
        __syncthreads();
    }

#pragma unroll
    for (int i = 0; i < 4; i++) {
        int gm = m0 + ty * 4 + i;
#pragma unroll
        for (int j = 0; j < 4; j++) {
            int gn = n0 + tx * 4 + j;
            if (gn < N) {
                float v = acc[i][j];
                if (bias) v += bias[gn];
                float* p = &C[(long)gm * ldc + gn];
                if (flags & 1) v += *p;
                *p = v;
            }
        }
    }
}

// ---------------------------------------------------------------------------
// Host-side orchestration
// ---------------------------------------------------------------------------
extern "C" void kernel_launch(void* const* d_in, const int* in_sizes, int n_in,
                              void* d_out, int out_size) {
    (void)in_sizes; (void)n_in; (void)out_size;

    const int*   tok     = (const int*)  d_in[0];
    const float* wte     = (const float*)d_in[1];
    const float* wpe     = (const float*)d_in[2];
    const float* ln1_w   = (const float*)d_in[3];
    const float* ln1_b   = (const float*)d_in[4];
    const float* attn_w  = (const float*)d_in[5];
    const float* attn_b  = (const float*)d_in[6];
    const float* aproj_w = (const float*)d_in[7];
    const float* aproj_b = (const float*)d_in[8];
    const float* ln2_w   = (const float*)d_in[9];
    const float* ln2_b   = (const float*)d_in[10];
    const float* fc_w    = (const float*)d_in[11];
    const float* fc_b    = (const float*)d_in[12];
    const float* mproj_w = (const float*)d_in[13];
    const float* mproj_b = (const float*)d_in[14];
    const float* lnf_w   = (const float*)d_in[15];
    const float* lnf_b   = (const float*)d_in[16];
    float* out = (float*)d_out;

    float *x, *ln, *qkv, *attn, *mid, *scores;
    cudaGetSymbolAddress((void**)&x,      g_x);
    cudaGetSymbolAddress((void**)&ln,     g_ln);
    cudaGetSymbolAddress((void**)&qkv,    g_qkv);
    cudaGetSymbolAddress((void**)&attn,   g_attn);
    cudaGetSymbolAddress((void**)&mid,    g_mid);
    cudaGetSymbolAddress((void**)&scores, g_scores);

    const int D = DMODEL;

    embed_kernel<<<NTOK, 256>>>(tok, wte, wpe, x);

    for (int l = 0; l < NLAYER; l++) {
        // h = LN1(x)
        layernorm_kernel<<<NTOK, 256>>>(x, ln1_w + l * D, ln1_b + l * D, ln);

        // qkv = h @ attn_w[l] + attn_b[l]   [2048, 2304]
        {
            dim3 g(3 * D / 128, NTOK / 128);
            gemm128_kernel<false><<<g, 256>>>(
                ln, D, 0, 0,
                attn_w + (long)l * D * 3 * D, 3 * D, 0, 0,
                qkv, 3 * D, 0, 0,
                attn_b + (long)l * 3 * D,
                NTOK, 3 * D, D, 1, 0);
        }

        // scores[z] = Q_z @ K_z^T  (z = b*12 + h); masked tiles skipped
        {
            dim3 g(NSEQ / 128, NSEQ / 128, 2 * NHEAD);
            gemm128_kernel<true><<<g, 256>>>(
                qkv,     3 * D, (long)NSEQ * 3 * D, HDIM,   // Q
                qkv + D, 3 * D, (long)NSEQ * 3 * D, HDIM,   // K
                scores, NSEQ, (long)NHEAD * NSEQ * NSEQ, (long)NSEQ * NSEQ,
                nullptr,
                NSEQ, NSEQ, HDIM, NHEAD, 4);
        }

        // causal softmax (applies 1/sqrt(64) scale, zero-fills masked region)
        softmax_kernel<<<dim3(NSEQ, 2 * NHEAD), 256>>>(scores);

        // attn[z] = P_z @ V_z with causal K truncation
        {
            dim3 g(1, NSEQ / 64, 2 * NHEAD);
            gemm64_kernel<<<g, 256>>>(
                scores, NSEQ, (long)NHEAD * NSEQ * NSEQ, (long)NSEQ * NSEQ,
                qkv + 2 * D, 3 * D, (long)NSEQ * 3 * D, HDIM,  // V
                attn, D, (long)NSEQ * D, HDIM,
                nullptr,
                NSEQ, HDIM, NSEQ, NHEAD, 8);
        }

        // x += attn @ aproj_w[l] + aproj_b[l]
        {
            dim3 g(D / 128, NTOK / 128);
            gemm128_kernel<false><<<g, 256>>>(
                attn, D, 0, 0,
                aproj_w + (long)l * D * D, D, 0, 0,
                x, D, 0, 0,
                aproj_b + (long)l * D,
                NTOK, D, D, 1, 1);
        }

        // h = LN2(x)
        layernorm_kernel<<<NTOK, 256>>>(x, ln2_w + l * D, ln2_b + l * D, ln);

        // mid = gelu(h @ fc_w[l] + fc_b[l])   [2048, 3072]
        {
            dim3 g(4 * D / 128, NTOK / 128);
            gemm128_kernel<false><<<g, 256>>>(
                ln, D, 0, 0,
                fc_w + (long)l * D * 4 * D, 4 * D, 0, 0,
                mid, 4 * D, 0, 0,
                fc_b + (long)l * 4 * D,
                NTOK, 4 * D, D, 1, 2);
        }

        // x += mid @ mproj_w[l] + mproj_b[l]
        {
            dim3 g(D / 128, NTOK / 128);
            gemm128_kernel<false><<<g, 256>>>(
                mid, 4 * D, 0, 0,
                mproj_w + (long)l * 4 * D * D, D, 0, 0,
                x, D, 0, 0,
                mproj_b + (long)l * D,
                NTOK, D, 4 * D, 1, 1);
        }
    }

    // final LN + tied lm_head: out = LN_f(x) @ wte^T   [2048, 50257]
    layernorm_kernel<<<NTOK, 256>>>(x, lnf_w, lnf_b, ln);
    {
        dim3 g((NVOCAB + 127) / 128, NTOK / 128);
        gemm128_kernel<true><<<g, 256>>>(
            ln, D, 0, 0,
            wte, D, 0, 0,
            out, NVOCAB, 0, 0,
            nullptr,
            NTOK, NVOCAB, D, 1, 0);
    }
}

// round 4
// speedup vs baseline: 1.8212x; 1.2718x over previous
#include <cuda_runtime.h>
#include <cuda_bf16.h>
#include <math.h>
#include <stdint.h>

// Problem constants
#define DMODEL 768
#define NTOK   2048          // B*N = 2*1024
#define NSEQ   1024
#define NHEAD  12
#define HDIM   64
#define NLAYER 12
#define NVOCAB 50257

// ---------------------------------------------------------------------------
// Device-global scratch (allocation-free; harness forbids cudaMalloc)
// ---------------------------------------------------------------------------
__device__ float g_x[NTOK * DMODEL];             // residual stream
__device__ float g_ln[NTOK * DMODEL];            // layernorm output
__device__ float g_qkv[NTOK * 3 * DMODEL];       // qkv projections
__device__ float g_attn[NTOK * DMODEL];          // attention output (B,N,D)
__device__ float g_mid[NTOK * 4 * DMODEL];       // MLP hidden
__device__ float g_scores[2 * NHEAD * NSEQ * NSEQ]; // attention scores/probs

// ---------------------------------------------------------------------------
// Block reduction helpers (blockDim.x == 256)
// ---------------------------------------------------------------------------
__device__ __forceinline__ float blockReduceSum(float v) {
    __shared__ float sh[8];
    int lane = threadIdx.x & 31, w = threadIdx.x >> 5;
#pragma unroll
    for (int o = 16; o; o >>= 1) v += __shfl_xor_sync(0xffffffffu, v, o);
    __syncthreads();
    if (lane == 0) sh[w] = v;
    __syncthreads();
    if (threadIdx.x == 0) {
        float s = sh[0];
#pragma unroll
        for (int i = 1; i < 8; i++) s += sh[i];
        sh[0] = s;
    }
    __syncthreads();
    return sh[0];
}

__device__ __forceinline__ float blockReduceMax(float v) {
    __shared__ float sh[8];
    int lane = threadIdx.x & 31, w = threadIdx.x >> 5;
#pragma unroll
    for (int o = 16; o; o >>= 1) v = fmaxf(v, __shfl_xor_sync(0xffffffffu, v, o));
    __syncthreads();
    if (lane == 0) sh[w] = v;
    __syncthreads();
    if (threadIdx.x == 0) {
        float s = sh[0];
#pragma unroll
        for (int i = 1; i < 8; i++) s = fmaxf(s, sh[i]);
        sh[0] = s;
    }
    __syncthreads();
    return sh[0];
}

// ---------------------------------------------------------------------------
// Embedding
// ---------------------------------------------------------------------------
__global__ void embed_kernel(const int* __restrict__ tok,
                             const float* __restrict__ wte,
                             const float* __restrict__ wpe,
                             float* __restrict__ x) {
    int t = blockIdx.x;
    int n = t & (NSEQ - 1);
    int id = tok[t];
    const float* w1 = wte + (long)id * DMODEL;
    const float* w2 = wpe + (long)n * DMODEL;
    float* xo = x + (long)t * DMODEL;
    for (int d = threadIdx.x; d < DMODEL; d += blockDim.x)
        xo[d] = w1[d] + w2[d];
}

// ---------------------------------------------------------------------------
// LayerNorm (row per block, 256 threads; D = 768 = 3*256)
// ---------------------------------------------------------------------------
__global__ __launch_bounds__(256) void layernorm_kernel(
    const float* __restrict__ x, const float* __restrict__ w,
    const float* __restrict__ b, float* __restrict__ out) {
    int t = blockIdx.x;
    const float* xr = x + (long)t * DMODEL;
    float* o = out + (long)t * DMODEL;
    int tid = threadIdx.x;

    float lx[3];
    float s = 0.f;
#pragma unroll
    for (int i = 0; i < 3; i++) { lx[i] = xr[tid + i * 256]; s += lx[i]; }
    s = blockReduceSum(s);
    float mu = s * (1.f / 768.f);

    float var = 0.f;
#pragma unroll
    for (int i = 0; i < 3; i++) { float d = lx[i] - mu; var += d * d; }
    var = blockReduceSum(var);
    float rstd = rsqrtf(var * (1.f / 768.f) + 1e-5f);

#pragma unroll
    for (int i = 0; i < 3; i++) {
        int d = tid + i * 256;
        o[d] = (lx[i] - mu) * rstd * w[d] + b[d];
    }
}

// ---------------------------------------------------------------------------
// Causal softmax; scale 1/8; zero-fills k>q so PV can truncate K exactly.
// ---------------------------------------------------------------------------
__global__ __launch_bounds__(256) void softmax_kernel(float* __restrict__ scores) {
    int q = blockIdx.x, z = blockIdx.y;
    float* row = scores + (long)z * NSEQ * NSEQ + (long)q * NSEQ;
    int tid = threadIdx.x;
    const float scale = 0.125f;

    float mx = -1e30f;
    for (int k = tid; k <= q; k += 256) mx = fmaxf(mx, row[k] * scale);
    mx = blockReduceMax(mx);

    float sum = 0.f;
    for (int k = tid; k <= q; k += 256) {
        float e = expf(row[k] * scale - mx);
        row[k] = e;
        sum += e;
    }
    sum = blockReduceSum(sum);
    float inv = 1.f / sum;

    for (int k = tid; k <= q; k += 256) row[k] *= inv;
    for (int k = q + 1 + tid; k < NSEQ; k += 256) row[k] = 0.f;
}

// ---------------------------------------------------------------------------
// Tensor-core GEMM via mma.sync bf16 with hi/lo split (3-MMA fp32 emulation).
//   C = A @ B (+bias)(+gelu)(+residual);  A fp32 [M,K], B fp32 ([K,N] or [N,K]).
//   128x128 block tile, BK=32, 256 thr = 8 warps (2m x 4n), warp tile 64x32.
//   flags: 1=residual, 2=exact GELU, 4=causal tile skip.
//   Requires M%128==0, K%32==0. N guarded everywhere (TB) / N%128==0 (non-TB).
// ---------------------------------------------------------------------------
#define KS 40                 // smem k-stride in bf16 elems (conflict-free)
#define TILE_E (128 * KS)     // elems per tile array

__device__ __forceinline__ void mma16816(float* d, const uint32_t* a, const uint32_t* b) {
    asm volatile(
        "mma.sync.aligned.m16n8k16.row.col.f32.bf16.bf16.f32 "
        "{%0,%1,%2,%3},{%4,%5,%6,%7},{%8,%9},{%0,%1,%2,%3};\n"
        : "+f"(d[0]), "+f"(d[1]), "+f"(d[2]), "+f"(d[3])
        : "r"(a[0]), "r"(a[1]), "r"(a[2]), "r"(a[3]), "r"(b[0]), "r"(b[1]));
}

template<bool TB>
__global__ __launch_bounds__(256) void bgemm_kernel(
    const float* __restrict__ A, int lda, long sA1, long sA2,
    const float* __restrict__ B, int ldb, long sB1, long sB2,
    float* __restrict__ C, int ldc, long sC1, long sC2,
    const float* __restrict__ bias,
    int M, int N, int K, int Z2, int flags) {

    int m0 = blockIdx.y * 128, n0 = blockIdx.x * 128;
    if ((flags & 4) && n0 > m0 + 127) return;

    int z = blockIdx.z;
    int z1 = z / Z2, z2 = z % Z2;
    A += (long)z1 * sA1 + (long)z2 * sA2;
    B += (long)z1 * sB1 + (long)z2 * sB2;
    C += (long)z1 * sC1 + (long)z2 * sC2;

    extern __shared__ __nv_bfloat16 S[];   // [2 bufs][Ah,Al,Bh,Bl][TILE_E]

    int tid = threadIdx.x, lane = tid & 31, wid = tid >> 5;
    int wm = wid & 1, wn = wid >> 1;
    int fr = lane >> 2, fc = lane & 3;

    float acc[4][4][4];
#pragma unroll
    for (int i = 0; i < 4; i++)
#pragma unroll
        for (int j = 0; j < 4; j++)
#pragma unroll
            for (int r = 0; r < 4; r++) acc[i][j][r] = 0.f;

    float4 av[4], bv[4];

    auto ldG = [&](int k0) {
#pragma unroll
        for (int i = 0; i < 4; i++) {
            int f = tid + i * 256;
            int m = f >> 3, kq = (f & 7) * 4;
            av[i] = *(const float4*)&A[(long)(m0 + m) * lda + k0 + kq];
            if (TB) {
                int gn = n0 + m;
                if (gn < N) bv[i] = *(const float4*)&B[(long)gn * ldb + k0 + kq];
                else        bv[i] = make_float4(0.f, 0.f, 0.f, 0.f);
            } else {
                int k = f >> 5, nq = (f & 31) * 4;
                bv[i] = *(const float4*)&B[(long)(k0 + k) * ldb + n0 + nq];
            }
        }
    };

    auto stS = [&](int buf) {
        __nv_bfloat16* Ah = S + buf * 4 * TILE_E;
        __nv_bfloat16* Al = Ah + TILE_E;
        __nv_bfloat16* Bh = Al + TILE_E;
        __nv_bfloat16* Bl = Bh + TILE_E;
#pragma unroll
        for (int i = 0; i < 4; i++) {
            int f = tid + i * 256;
            int m = f >> 3, kq = (f & 7) * 4;
            float va[4] = {av[i].x, av[i].y, av[i].z, av[i].w};
#pragma unroll
            for (int j = 0; j < 4; j++) {
                __nv_bfloat16 h = __float2bfloat16(va[j]);
                Ah[m * KS + kq + j] = h;
                Al[m * KS + kq + j] = __float2bfloat16(va[j] - __bfloat162float(h));
            }
            float vb[4] = {bv[i].x, bv[i].y, bv[i].z, bv[i].w};
            if (TB) {
#pragma unroll
                for (int j = 0; j < 4; j++) {
                    __nv_bfloat16 h = __float2bfloat16(vb[j]);
                    Bh[m * KS + kq + j] = h;
                    Bl[m * KS + kq + j] = __float2bfloat16(vb[j] - __bfloat162float(h));
                }
            } else {
                int k = f >> 5, nq = (f & 31) * 4;
#pragma unroll
                for (int j = 0; j < 4; j++) {
                    __nv_bfloat16 h = __float2bfloat16(vb[j]);
                    Bh[(nq + j) * KS + k] = h;
                    Bl[(nq + j) * KS + k] = __float2bfloat16(vb[j] - __bfloat162float(h));
                }
            }
        }
    };

    ldG(0);
    stS(0);
    __syncthreads();

    int KT = K >> 5;
    int buf = 0;
    for (int kt = 0; kt < KT; kt++) {
        if (kt + 1 < KT) ldG((kt + 1) << 5);

        const __nv_bfloat16* Ah = S + buf * 4 * TILE_E;
        const __nv_bfloat16* Al = Ah + TILE_E;
        const __nv_bfloat16* Bh = Al + TILE_E;
        const __nv_bfloat16* Bl = Bh + TILE_E;

#pragma unroll
        for (int ks = 0; ks < 32; ks += 16) {
            uint32_t ah[4][4], bh[4][2];
            // hi fragments
#pragma unroll
            for (int mi = 0; mi < 4; mi++) {
                int r = wm * 64 + mi * 16 + fr;
                ah[mi][0] = *(const uint32_t*)&Ah[r * KS + ks + fc * 2];
                ah[mi][1] = *(const uint32_t*)&Ah[(r + 8) * KS + ks + fc * 2];
                ah[mi][2] = *(const uint32_t*)&Ah[r * KS + ks + 8 + fc * 2];
                ah[mi][3] = *(const uint32_t*)&Ah[(r + 8) * KS + ks + 8 + fc * 2];
            }
#pragma unroll
            for (int ni = 0; ni < 4; ni++) {
                int c = wn * 32 + ni * 8 + fr;
                bh[ni][0] = *(const uint32_t*)&Bh[c * KS + ks + fc * 2];
                bh[ni][1] = *(const uint32_t*)&Bh[c * KS + ks + 8 + fc * 2];
            }
            // hi * hi
#pragma unroll
            for (int mi = 0; mi < 4; mi++)
#pragma unroll
                for (int ni = 0; ni < 4; ni++)
                    mma16816(acc[mi][ni], ah[mi], bh[ni]);
            // lo(A) * hi(B)
#pragma unroll
            for (int mi = 0; mi < 4; mi++) {
                uint32_t al[4];
                int r = wm * 64 + mi * 16 + fr;
                al[0] = *(const uint32_t*)&Al[r * KS + ks + fc * 2];
                al[1] = *(const uint32_t*)&Al[(r + 8) * KS + ks + fc * 2];
                al[2] = *(const uint32_t*)&Al[r * KS + ks + 8 + fc * 2];
                al[3] = *(const uint32_t*)&Al[(r + 8) * KS + ks + 8 + fc * 2];
#pragma unroll
                for (int ni = 0; ni < 4; ni++)
                    mma16816(acc[mi][ni], al, bh[ni]);
            }
            // hi(A) * lo(B)
#pragma unroll
            for (int ni = 0; ni < 4; ni++) {
                uint32_t bl[2];
                int c = wn * 32 + ni * 8 + fr;
                bl[0] = *(const uint32_t*)&Bl[c * KS + ks + fc * 2];
                bl[1] = *(const uint32_t*)&Bl[c * KS + ks + 8 + fc * 2];
#pragma unroll
                for (int mi = 0; mi < 4; mi++)
                    mma16816(acc[mi][ni], ah[mi], bl);
            }
        }

        if (kt + 1 < KT) {
            stS(buf ^ 1);
            __syncthreads();
            buf ^= 1;
        }
    }

    // Epilogue
#pragma unroll
    for (int mi = 0; mi < 4; mi++) {
        int gm0 = m0 + wm * 64 + mi * 16 + fr;
#pragma unroll
        for (int ni = 0; ni < 4; ni++) {
            int gn = n0 + wn * 32 + ni * 8 + fc * 2;
#pragma unroll
            for (int r = 0; r < 4; r++) {
                int gm = gm0 + (r >= 2 ? 8 : 0);
                int gc = gn + (r & 1);
                if (gc < N) {
                    float v = acc[mi][ni][r];
                    if (bias) v += bias[gc];
                    if (flags & 2) v = 0.5f * v * (1.f + erff(v * 0.70710678118654752f));
                    float* p = &C[(long)gm * ldc + gc];
                    if (flags & 1) v += *p;
                    *p = v;
                }
            }
        }
    }
}

// ---------------------------------------------------------------------------
// Small fp32 GEMM (64x64 tile, BK=16) for PV (N=64).
//   flags: 8 = causal K truncation (K_eff = min(K, m0+64)).
// ---------------------------------------------------------------------------
__global__ __launch_bounds__(256) void gemm64_kernel(
    const float* __restrict__ A, int lda, long sA1, long sA2,
    const float* __restrict__ B, int ldb, long sB1, long sB2,
    float* __restrict__ C, int ldc, long sC1, long sC2,
    const float* __restrict__ bias,
    int M, int N, int K, int Z2, int flags) {

    int m0 = blockIdx.y * 64, n0 = blockIdx.x * 64;

    int z = blockIdx.z;
    int z1 = z / Z2, z2 = z % Z2;
    A += (long)z1 * sA1 + (long)z2 * sA2;
    B += (long)z1 * sB1 + (long)z2 * sB2;
    C += (long)z1 * sC1 + (long)z2 * sC2;

    __shared__ float As[16][64];
    __shared__ float Bs[16][64];

    int tid = threadIdx.x;
    int tx = tid & 15, ty = tid >> 4;
    float acc[4][4] = {};

    int Kend = (flags & 8) ? min(K, m0 + 64) : K;

    for (int k0 = 0; k0 < Kend; k0 += 16) {
#pragma unroll
        for (int i = 0; i < 4; i++) {
            int idx = tid + i * 256;
            int m = idx >> 4, k = idx & 15;
            As[k][m] = A[(long)(m0 + m) * lda + (k0 + k)];
        }
#pragma unroll
        for (int i = 0; i < 4; i++) {
            int idx = tid + i * 256;
            int k = idx >> 6, n = idx & 63;
            int gn = n0 + n;
            Bs[k][n] = (gn < N) ? B[(long)(k0 + k) * ldb + gn] : 0.f;
        }
        __syncthreads();
#pragma unroll
        for (int k = 0; k < 16; k++) {
            float4 a4 = *(const float4*)&As[k][ty * 4];
            float4 b4 = *(const float4*)&Bs[k][tx * 4];
            float ra[4] = {a4.x, a4.y, a4.z, a4.w};
            float rb[4] = {b4.x, b4.y, b4.z, b4.w};
#pragma unroll
            for (int i = 0; i < 4; i++)
#pragma unroll
                for (int j = 0; j < 4; j++)
                    acc[i][j] = fmaf(ra[i], rb[j], acc[i][j]);
        }
        __syncthreads();
    }

#pragma unroll
    for (int i = 0; i < 4; i++) {
        int gm = m0 + ty * 4 + i;
#pragma unroll
        for (int j = 0; j < 4; j++) {
            int gn = n0 + tx * 4 + j;
            if (gn < N) {
                float v = acc[i][j];
                if (bias) v += bias[gn];
                float* p = &C[(long)gm * ldc + gn];
                if (flags & 1) v += *p;
                *p = v;
            }
        }
    }
}

// ---------------------------------------------------------------------------
// Host-side orchestration
// ---------------------------------------------------------------------------
extern "C" void kernel_launch(void* const* d_in, const int* in_sizes, int n_in,
                              void* d_out, int out_size) {
    (void)in_sizes; (void)n_in; (void)out_size;

    const int*   tok     = (const int*)  d_in[0];
    const float* wte     = (const float*)d_in[1];
    const float* wpe     = (const float*)d_in[2];
    const float* ln1_w   = (const float*)d_in[3];
    const float* ln1_b   = (const float*)d_in[4];
    const float* attn_w  = (const float*)d_in[5];
    const float* attn_b  = (const float*)d_in[6];
    const float* aproj_w = (const float*)d_in[7];
    const float* aproj_b = (const float*)d_in[8];
    const float* ln2_w   = (const float*)d_in[9];
    const float* ln2_b   = (const float*)d_in[10];
    const float* fc_w    = (const float*)d_in[11];
    const float* fc_b    = (const float*)d_in[12];
    const float* mproj_w = (const float*)d_in[13];
    const float* mproj_b = (const float*)d_in[14];
    const float* lnf_w   = (const float*)d_in[15];
    const float* lnf_b   = (const float*)d_in[16];
    float* out = (float*)d_out;

    float *x, *ln, *qkv, *attn, *mid, *scores;
    cudaGetSymbolAddress((void**)&x,      g_x);
    cudaGetSymbolAddress((void**)&ln,     g_ln);
    cudaGetSymbolAddress((void**)&qkv,    g_qkv);
    cudaGetSymbolAddress((void**)&attn,   g_attn);
    cudaGetSymbolAddress((void**)&mid,    g_mid);
    cudaGetSymbolAddress((void**)&scores, g_scores);

    const int D = DMODEL;
    const int SMEM = 2 * 4 * TILE_E * (int)sizeof(__nv_bfloat16);  // 81920

    cudaFuncSetAttribute(bgemm_kernel<false>,
                         cudaFuncAttributeMaxDynamicSharedMemorySize, SMEM);
    cudaFuncSetAttribute(bgemm_kernel<true>,
                         cudaFuncAttributeMaxDynamicSharedMemorySize, SMEM);

    embed_kernel<<<NTOK, 256>>>(tok, wte, wpe, x);

    for (int l = 0; l < NLAYER; l++) {
        layernorm_kernel<<<NTOK, 256>>>(x, ln1_w + l * D, ln1_b + l * D, ln);

        // qkv = h @ attn_w[l] + attn_b[l]   [2048, 2304]
        {
            dim3 g(3 * D / 128, NTOK / 128);
            bgemm_kernel<false><<<g, 256, SMEM>>>(
                ln, D, 0, 0,
                attn_w + (long)l * D * 3 * D, 3 * D, 0, 0,
                qkv, 3 * D, 0, 0,
                attn_b + (long)l * 3 * D,
                NTOK, 3 * D, D, 1, 0);
        }

        // scores[z] = Q_z @ K_z^T
        {
            dim3 g(NSEQ / 128, NSEQ / 128, 2 * NHEAD);
            bgemm_kernel<true><<<g, 256, SMEM>>>(
                qkv,     3 * D, (long)NSEQ * 3 * D, HDIM,
                qkv + D, 3 * D, (long)NSEQ * 3 * D, HDIM,
                scores, NSEQ, (long)NHEAD * NSEQ * NSEQ, (long)NSEQ * NSEQ,
                nullptr,
                NSEQ, NSEQ, HDIM, NHEAD, 4);
        }

        softmax_kernel<<<dim3(NSEQ, 2 * NHEAD), 256>>>(scores);

        // attn[z] = P_z @ V_z with causal K truncation (fp32 path)
        {
            dim3 g(1, NSEQ / 64, 2 * NHEAD);
            gemm64_kernel<<<g, 256>>>(
                scores, NSEQ, (long)NHEAD * NSEQ * NSEQ, (long)NSEQ * NSEQ,
                qkv + 2 * D, 3 * D, (long)NSEQ * 3 * D, HDIM,
                attn, D, (long)NSEQ * D, HDIM,
                nullptr,
                NSEQ, HDIM, NSEQ, NHEAD, 8);
        }

        // x += attn @ aproj_w[l] + aproj_b[l]
        {
            dim3 g(D / 128, NTOK / 128);
            bgemm_kernel<false><<<g, 256, SMEM>>>(
                attn, D, 0, 0,
                aproj_w + (long)l * D * D, D, 0, 0,
                x, D, 0, 0,
                aproj_b + (long)l * D,
                NTOK, D, D, 1, 1);
        }

        layernorm_kernel<<<NTOK, 256>>>(x, ln2_w + l * D, ln2_b + l * D, ln);

        // mid = gelu(h @ fc_w[l] + fc_b[l])   [2048, 3072]
        {
            dim3 g(4 * D / 128, NTOK / 128);
            bgemm_kernel<false><<<g, 256, SMEM>>>(
                ln, D, 0, 0,
                fc_w + (long)l * D * 4 * D, 4 * D, 0, 0,
                mid, 4 * D, 0, 0,
                fc_b + (long)l * 4 * D,
                NTOK, 4 * D, D, 1, 2);
        }

        // x += mid @ mproj_w[l] + mproj_b[l]
        {
            dim3 g(D / 128, NTOK / 128);
            bgemm_kernel<false><<<g, 256, SMEM>>>(
                mid, 4 * D, 0, 0,
                mproj_w + (long)l * 4 * D * D, D, 0, 0,
                x, D, 0, 0,
                mproj_b + (long)l * D,
                NTOK, D, 4 * D, 1, 1);
        }
    }

    // final LN + tied lm_head: out = LN_f(x) @ wte^T   [2048, 50257]
    layernorm_kernel<<<NTOK, 256>>>(x, lnf_w, lnf_b, ln);
    {
        dim3 g((NVOCAB + 127) / 128, NTOK / 128);
        bgemm_kernel<true><<<g, 256, SMEM>>>(
            ln, D, 0, 0,
            wte, D, 0, 0,
            out, NVOCAB, 0, 0,
            nullptr,
            NTOK, NVOCAB, D, 1, 0);
    }
}

// round 5
// speedup vs baseline: 2.5961x; 1.4255x over previous
#include <cuda_runtime.h>
#include <cuda_bf16.h>
#include <math.h>
#include <stdint.h>

// Problem constants
#define DMODEL 768
#define NTOK   2048          // B*N = 2*1024
#define NSEQ   1024
#define NHEAD  12
#define HDIM   64
#define NLAYER 12
#define NVOCAB 50257

#define KS 40                 // smem k-stride in bf16 elems (conflict-free)
#define TILE_E (128 * KS)     // elems per smem tile array

typedef __nv_bfloat16 bf16;

// ---------------------------------------------------------------------------
// Device-global scratch (allocation-free)
// ---------------------------------------------------------------------------
__device__ float g_x[NTOK * DMODEL];                  // residual stream (fp32)
__device__ float g_qkv[NTOK * 3 * DMODEL];            // qkv fp32 (V read by PV)
__device__ float g_scores[2 * NHEAD * NSEQ * NSEQ];   // scores/probs fp32

// activations, bf16 hi/lo
__device__ bf16 g_lnh[NTOK * DMODEL],      g_lnl[NTOK * DMODEL];
__device__ bf16 g_qkvh[NTOK * 3 * DMODEL], g_qkvl[NTOK * 3 * DMODEL];
__device__ bf16 g_attnh[NTOK * DMODEL],    g_attnl[NTOK * DMODEL];
__device__ bf16 g_midh[NTOK * 4 * DMODEL], g_midl[NTOK * 4 * DMODEL];

// weights, transposed to [N,K], bf16 hi/lo
__device__ bf16 g_wqkvh[NLAYER * 3 * DMODEL * DMODEL], g_wqkvl[NLAYER * 3 * DMODEL * DMODEL];
__device__ bf16 g_waph [NLAYER * DMODEL * DMODEL],     g_wapl [NLAYER * DMODEL * DMODEL];
__device__ bf16 g_wfch [NLAYER * 4 * DMODEL * DMODEL], g_wfcl [NLAYER * 4 * DMODEL * DMODEL];
__device__ bf16 g_wmph [NLAYER * DMODEL * 4 * DMODEL], g_wmpl [NLAYER * DMODEL * 4 * DMODEL];
__device__ bf16 g_wteh [(long)NVOCAB * DMODEL],        g_wtel [(long)NVOCAB * DMODEL];

// ---------------------------------------------------------------------------
// Helpers
// ---------------------------------------------------------------------------
__device__ __forceinline__ float blockReduceSum(float v) {
    __shared__ float sh[8];
    int lane = threadIdx.x & 31, w = threadIdx.x >> 5;
#pragma unroll
    for (int o = 16; o; o >>= 1) v += __shfl_xor_sync(0xffffffffu, v, o);
    __syncthreads();
    if (lane == 0) sh[w] = v;
    __syncthreads();
    if (threadIdx.x == 0) {
        float s = sh[0];
#pragma unroll
        for (int i = 1; i < 8; i++) s += sh[i];
        sh[0] = s;
    }
    __syncthreads();
    return sh[0];
}

__device__ __forceinline__ float blockReduceMax(float v) {
    __shared__ float sh[8];
    int lane = threadIdx.x & 31, w = threadIdx.x >> 5;
#pragma unroll
    for (int o = 16; o; o >>= 1) v = fmaxf(v, __shfl_xor_sync(0xffffffffu, v, o));
    __syncthreads();
    if (lane == 0) sh[w] = v;
    __syncthreads();
    if (threadIdx.x == 0) {
        float s = sh[0];
#pragma unroll
        for (int i = 1; i < 8; i++) s = fmaxf(s, sh[i]);
        sh[0] = s;
    }
    __syncthreads();
    return sh[0];
}

__device__ __forceinline__ void cp16(uint32_t saddr, const void* gaddr) {
    asm volatile("cp.async.cg.shared.global [%0], [%1], 16;\n"
                 :: "r"(saddr), "l"(gaddr));
}

__device__ __forceinline__ void mma16816(float* d, const uint32_t* a, const uint32_t* b) {
    asm volatile(
        "mma.sync.aligned.m16n8k16.row.col.f32.bf16.bf16.f32 "
        "{%0,%1,%2,%3},{%4,%5,%6,%7},{%8,%9},{%0,%1,%2,%3};\n"
        : "+f"(d[0]), "+f"(d[1]), "+f"(d[2]), "+f"(d[3])
        : "r"(a[0]), "r"(a[1]), "r"(a[2]), "r"(a[3]), "r"(b[0]), "r"(b[1]));
}

// ---------------------------------------------------------------------------
// Weight prep: transpose+split W[z][K][N] -> T[z][N][K] hi/lo bf16
// block (32,8), grid (K/32, N/32, Z)
// ---------------------------------------------------------------------------
__global__ void tsplit_kernel(const float* __restrict__ W,
                              bf16* __restrict__ Th, bf16* __restrict__ Tl,
                              int K, int N) {
    __shared__ float t[32][33];
    long zoff = (long)blockIdx.z * K * N;
    W += zoff; Th += zoff; Tl += zoff;
    int k0 = blockIdx.x * 32, n0 = blockIdx.y * 32;
    int tx = threadIdx.x, ty = threadIdx.y;
#pragma unroll
    for (int i = 0; i < 4; i++)
        t[ty + i * 8][tx] = W[(long)(k0 + ty + i * 8) * N + n0 + tx];
    __syncthreads();
#pragma unroll
    for (int i = 0; i < 4; i++) {
        int n = n0 + ty + i * 8, k = k0 + tx;
        float v = t[tx][ty + i * 8];
        bf16 h = __float2bfloat16(v);
        Th[(long)n * K + k] = h;
        Tl[(long)n * K + k] = __float2bfloat16(v - __bfloat162float(h));
    }
}

// Elementwise split (wte: already [V, D] = [N, K])
__global__ void split_kernel(const float* __restrict__ in,
                             bf16* __restrict__ h, bf16* __restrict__ l, long n) {
    long i = (long)blockIdx.x * 256 + threadIdx.x;
    if (i < n) {
        float v = in[i];
        bf16 hi = __float2bfloat16(v);
        h[i] = hi;
        l[i] = __float2bfloat16(v - __bfloat162float(hi));
    }
}

// ---------------------------------------------------------------------------
// Embedding
// ---------------------------------------------------------------------------
__global__ void embed_kernel(const int* __restrict__ tok,
                             const float* __restrict__ wte,
                             const float* __restrict__ wpe,
                             float* __restrict__ x) {
    int t = blockIdx.x;
    int n = t & (NSEQ - 1);
    int id = tok[t];
    const float* w1 = wte + (long)id * DMODEL;
    const float* w2 = wpe + (long)n * DMODEL;
    float* xo = x + (long)t * DMODEL;
    for (int d = threadIdx.x; d < DMODEL; d += blockDim.x)
        xo[d] = w1[d] + w2[d];
}

// ---------------------------------------------------------------------------
// LayerNorm: fp32 in -> bf16 hi/lo out
// ---------------------------------------------------------------------------
__global__ __launch_bounds__(256) void layernorm_kernel(
    const float* __restrict__ x, const float* __restrict__ w,
    const float* __restrict__ b,
    bf16* __restrict__ oh, bf16* __restrict__ ol) {
    int t = blockIdx.x;
    const float* xr = x + (long)t * DMODEL;
    int tid = threadIdx.x;

    float lx[3];
    float s = 0.f;
#pragma unroll
    for (int i = 0; i < 3; i++) { lx[i] = xr[tid + i * 256]; s += lx[i]; }
    s = blockReduceSum(s);
    float mu = s * (1.f / 768.f);

    float var = 0.f;
#pragma unroll
    for (int i = 0; i < 3; i++) { float d = lx[i] - mu; var += d * d; }
    var = blockReduceSum(var);
    float rstd = rsqrtf(var * (1.f / 768.f) + 1e-5f);

#pragma unroll
    for (int i = 0; i < 3; i++) {
        int d = tid + i * 256;
        float v = (lx[i] - mu) * rstd * w[d] + b[d];
        bf16 h = __float2bfloat16(v);
        oh[(long)t * DMODEL + d] = h;
        ol[(long)t * DMODEL + d] = __float2bfloat16(v - __bfloat162float(h));
    }
}

// ---------------------------------------------------------------------------
// Causal softmax; scale 1/8; zero-fills k>q so PV can truncate K exactly.
// ---------------------------------------------------------------------------
__global__ __launch_bounds__(256) void softmax_kernel(float* __restrict__ scores) {
    int q = blockIdx.x, z = blockIdx.y;
    float* row = scores + (long)z * NSEQ * NSEQ + (long)q * NSEQ;
    int tid = threadIdx.x;
    const float scale = 0.125f;

    float mx = -1e30f;
    for (int k = tid; k <= q; k += 256) mx = fmaxf(mx, row[k] * scale);
    mx = blockReduceMax(mx);

    float sum = 0.f;
    for (int k = tid; k <= q; k += 256) {
        float e = expf(row[k] * scale - mx);
        row[k] = e;
        sum += e;
    }
    sum = blockReduceSum(sum);
    float inv = 1.f / sum;

    for (int k = tid; k <= q; k += 256) row[k] *= inv;
    for (int k = q + 1 + tid; k < NSEQ; k += 256) row[k] = 0.f;
}

// ---------------------------------------------------------------------------
// Tensor-core GEMM, 3-MMA bf16 hi/lo emulation, pre-split inputs.
//   A: [M,K] bf16 hi/lo, row stride lda.  B: [N,K] bf16 hi/lo, row stride ldb.
//   128x128 tile, BK=32, 256 thr = 8 warps (2m x 4n), warp tile 64x32.
//   cp.async double-buffered. flags: 1=residual add (fp32 C), 2=exact GELU,
//   4=causal tile skip, 8=write fp32 C, 16=write bf16 hi/lo (Ch, Cl).
//   Requires M%128==0, K%32==0; N guarded.
// ---------------------------------------------------------------------------
__global__ __launch_bounds__(256, 2) void bgemm_kernel(
    const bf16* __restrict__ Ah, const bf16* __restrict__ Al,
    int lda, long sA1, long sA2,
    const bf16* __restrict__ Bh, const bf16* __restrict__ Bl,
    int ldb, long sB1, long sB2,
    float* __restrict__ C, bf16* __restrict__ Ch, bf16* __restrict__ Cl,
    int ldc, long sC1, long sC2,
    const float* __restrict__ bias,
    int M, int N, int K, int Z2, int flags) {

    int m0 = blockIdx.y * 128, n0 = blockIdx.x * 128;
    if ((flags & 4) && n0 > m0 + 127) return;

    int z = blockIdx.z;
    int z1 = z / Z2, z2 = z % Z2;
    long aoff = (long)z1 * sA1 + (long)z2 * sA2;
    long boff = (long)z1 * sB1 + (long)z2 * sB2;
    long coff = (long)z1 * sC1 + (long)z2 * sC2;
    Ah += aoff; Al += aoff;
    Bh += boff; Bl += boff;

    extern __shared__ bf16 S[];   // [2 bufs][Ah,Al,Bh,Bl][TILE_E]
    uint32_t sbase = (uint32_t)__cvta_generic_to_shared(S);

    int tid = threadIdx.x, lane = tid & 31, wid = tid >> 5;
    int wm = wid & 1, wn = wid >> 1;
    int fr = lane >> 2, fc = lane & 3;

    int r2 = tid >> 1;            // row 0..127 (2 threads/row)
    int c2 = (tid & 1) * 16;      // elem offset: 0 or 16 (two 8-elem chunks)

    float acc[4][4][4];
#pragma unroll
    for (int i = 0; i < 4; i++)
#pragma unroll
        for (int j = 0; j < 4; j++)
#pragma unroll
            for (int r = 0; r < 4; r++) acc[i][j][r] = 0.f;

    auto ldStage = [&](int k0, int bufi) {
        uint32_t sb = sbase + bufi * (4 * TILE_E * 2);
        uint32_t sa = sb + r2 * (KS * 2) + c2 * 2;
        const bf16* ga = Ah + (long)(m0 + r2) * lda + k0 + c2;
        cp16(sa, ga);            cp16(sa + 16, ga + 8);
        ga = Al + (long)(m0 + r2) * lda + k0 + c2;
        cp16(sa + TILE_E * 2, ga); cp16(sa + TILE_E * 2 + 16, ga + 8);
        int gn = n0 + r2;
        uint32_t sbB = sb + 2 * TILE_E * 2 + r2 * (KS * 2) + c2 * 2;
        if (gn < N) {
            const bf16* gb = Bh + (long)gn * ldb + k0 + c2;
            cp16(sbB, gb);            cp16(sbB + 16, gb + 8);
            gb = Bl + (long)gn * ldb + k0 + c2;
            cp16(sbB + TILE_E * 2, gb); cp16(sbB + TILE_E * 2 + 16, gb + 8);
        } else {
            uint4 zz = make_uint4(0, 0, 0, 0);
            bf16* p = S + bufi * 4 * TILE_E + 2 * TILE_E + r2 * KS + c2;
            *(uint4*)p = zz; *(uint4*)(p + 8) = zz;
            p += TILE_E;
            *(uint4*)p = zz; *(uint4*)(p + 8) = zz;
        }
        asm volatile("cp.async.commit_group;\n" ::: "memory");
    };

    ldStage(0, 0);

    int KT = K >> 5;
    int buf = 0;
    for (int kt = 0; kt < KT; kt++) {
        asm volatile("cp.async.wait_group 0;\n" ::: "memory");
        __syncthreads();
        if (kt + 1 < KT) ldStage((kt + 1) << 5, buf ^ 1);

        const bf16* sAh = S + buf * 4 * TILE_E;
        const bf16* sAl = sAh + TILE_E;
        const bf16* sBh = sAl + TILE_E;
        const bf16* sBl = sBh + TILE_E;

#pragma unroll
        for (int ks = 0; ks < 32; ks += 16) {
            uint32_t ah[4][4], bh[4][2];
#pragma unroll
            for (int mi = 0; mi < 4; mi++) {
                int r = wm * 64 + mi * 16 + fr;
                ah[mi][0] = *(const uint32_t*)&sAh[r * KS + ks + fc * 2];
                ah[mi][1] = *(const uint32_t*)&sAh[(r + 8) * KS + ks + fc * 2];
                ah[mi][2] = *(const uint32_t*)&sAh[r * KS + ks + 8 + fc * 2];
                ah[mi][3] = *(const uint32_t*)&sAh[(r + 8) * KS + ks + 8 + fc * 2];
            }
#pragma unroll
            for (int ni = 0; ni < 4; ni++) {
                int c = wn * 32 + ni * 8 + fr;
                bh[ni][0] = *(const uint32_t*)&sBh[c * KS + ks + fc * 2];
                bh[ni][1] = *(const uint32_t*)&sBh[c * KS + ks + 8 + fc * 2];
            }
#pragma unroll
            for (int mi = 0; mi < 4; mi++)
#pragma unroll
                for (int ni = 0; ni < 4; ni++)
                    mma16816(acc[mi][ni], ah[mi], bh[ni]);
#pragma unroll
            for (int mi = 0; mi < 4; mi++) {
                uint32_t al[4];
                int r = wm * 64 + mi * 16 + fr;
                al[0] = *(const uint32_t*)&sAl[r * KS + ks + fc * 2];
                al[1] = *(const uint32_t*)&sAl[(r + 8) * KS + ks + fc * 2];
                al[2] = *(const uint32_t*)&sAl[r * KS + ks + 8 + fc * 2];
                al[3] = *(const uint32_t*)&sAl[(r + 8) * KS + ks + 8 + fc * 2];
#pragma unroll
                for (int ni = 0; ni < 4; ni++)
                    mma16816(acc[mi][ni], al, bh[ni]);
            }
#pragma unroll
            for (int ni = 0; ni < 4; ni++) {
                uint32_t bl[2];
                int c = wn * 32 + ni * 8 + fr;
                bl[0] = *(const uint32_t*)&sBl[c * KS + ks + fc * 2];
                bl[1] = *(const uint32_t*)&sBl[c * KS + ks + 8 + fc * 2];
#pragma unroll
                for (int mi = 0; mi < 4; mi++)
                    mma16816(acc[mi][ni], ah[mi], bl);
            }
        }
        __syncthreads();
        buf ^= 1;
    }

    // Epilogue
#pragma unroll
    for (int mi = 0; mi < 4; mi++) {
        int gm0 = m0 + wm * 64 + mi * 16 + fr;
#pragma unroll
        for (int ni = 0; ni < 4; ni++) {
            int gn = n0 + wn * 32 + ni * 8 + fc * 2;
#pragma unroll
            for (int r = 0; r < 4; r++) {
                int gm = gm0 + (r >= 2 ? 8 : 0);
                int gc = gn + (r & 1);
                if (gc < N) {
                    float v = acc[mi][ni][r];
                    if (bias) v += bias[gc];
                    if (flags & 2) v = 0.5f * v * (1.f + erff(v * 0.70710678118654752f));
                    long idx = coff + (long)gm * ldc + gc;
                    if (flags & 1) v += C[idx];
                    if (flags & 8) C[idx] = v;
                    if (flags & 16) {
                        bf16 h = __float2bfloat16(v);
                        Ch[idx] = h;
                        Cl[idx] = __float2bfloat16(v - __bfloat162float(h));
                    }
                }
            }
        }
    }
}

// ---------------------------------------------------------------------------
// Small fp32 GEMM for PV (N=64), causal K truncation; writes bf16 hi/lo.
// ---------------------------------------------------------------------------
__global__ __launch_bounds__(256) void gemm64_kernel(
    const float* __restrict__ A, int lda, long sA1, long sA2,
    const float* __restrict__ B, int ldb, long sB1, long sB2,
    bf16* __restrict__ Ch, bf16* __restrict__ Cl,
    int ldc, long sC1, long sC2,
    int M, int N, int K, int Z2) {

    int m0 = blockIdx.y * 64, n0 = blockIdx.x * 64;

    int z = blockIdx.z;
    int z1 = z / Z2, z2 = z % Z2;
    A += (long)z1 * sA1 + (long)z2 * sA2;
    B += (long)z1 * sB1 + (long)z2 * sB2;
    long coff = (long)z1 * sC1 + (long)z2 * sC2;

    __shared__ float As[16][64];
    __shared__ float Bs[16][64];

    int tid = threadIdx.x;
    int tx = tid & 15, ty = tid >> 4;
    float acc[4][4] = {};

    int Kend = min(K, m0 + 64);   // causal truncation

    for (int k0 = 0; k0 < Kend; k0 += 16) {
#pragma unroll
        for (int i = 0; i < 4; i++) {
            int idx = tid + i * 256;
            int m = idx >> 4, k = idx & 15;
            As[k][m] = A[(long)(m0 + m) * lda + (k0 + k)];
        }
#pragma unroll
        for (int i = 0; i < 4; i++) {
            int idx = tid + i * 256;
            int k = idx >> 6, n = idx & 63;
            int gn = n0 + n;
            Bs[k][n] = (gn < N) ? B[(long)(k0 + k) * ldb + gn] : 0.f;
        }
        __syncthreads();
#pragma unroll
        for (int k = 0; k < 16; k++) {
            float4 a4 = *(const float4*)&As[k][ty * 4];
            float4 b4 = *(const float4*)&Bs[k][tx * 4];
            float ra[4] = {a4.x, a4.y, a4.z, a4.w};
            float rb[4] = {b4.x, b4.y, b4.z, b4.w};
#pragma unroll
            for (int i = 0; i < 4; i++)
#pragma unroll
                for (int j = 0; j < 4; j++)
                    acc[i][j] = fmaf(ra[i], rb[j], acc[i][j]);
        }
        __syncthreads();
    }

#pragma unroll
    for (int i = 0; i < 4; i++) {
        int gm = m0 + ty * 4 + i;
#pragma unroll
        for (int j = 0; j < 4; j++) {
            int gn = n0 + tx * 4 + j;
            if (gn < N) {
                float v = acc[i][j];
                long idx = coff + (long)gm * ldc + gn;
                bf16 h = __float2bfloat16(v);
                Ch[idx] = h;
                Cl[idx] = __float2bfloat16(v - __bfloat162float(h));
            }
        }
    }
}

// ---------------------------------------------------------------------------
// Host-side orchestration
// ---------------------------------------------------------------------------
extern "C" void kernel_launch(void* const* d_in, const int* in_sizes, int n_in,
                              void* d_out, int out_size) {
    (void)in_sizes; (void)n_in; (void)out_size;

    const int*   tok     = (const int*)  d_in[0];
    const float* wte     = (const float*)d_in[1];
    const float* wpe     = (const float*)d_in[2];
    const float* ln1_w   = (const float*)d_in[3];
    const float* ln1_b   = (const float*)d_in[4];
    const float* attn_w  = (const float*)d_in[5];
    const float* attn_b  = (const float*)d_in[6];
    const float* aproj_w = (const float*)d_in[7];
    const float* aproj_b = (const float*)d_in[8];
    const float* ln2_w   = (const float*)d_in[9];
    const float* ln2_b   = (const float*)d_in[10];
    const float* fc_w    = (const float*)d_in[11];
    const float* fc_b    = (const float*)d_in[12];
    const float* mproj_w = (const float*)d_in[13];
    const float* mproj_b = (const float*)d_in[14];
    const float* lnf_w   = (const float*)d_in[15];
    const float* lnf_b   = (const float*)d_in[16];
    float* out = (float*)d_out;

    float *x, *qkv, *scores;
    bf16 *lnh, *lnl, *qkvh, *qkvl, *attnh, *attnl, *midh, *midl;
    bf16 *wqkvh, *wqkvl, *waph, *wapl, *wfch, *wfcl, *wmph, *wmpl, *wteh, *wtel;
    cudaGetSymbolAddress((void**)&x,      g_x);
    cudaGetSymbolAddress((void**)&qkv,    g_qkv);
    cudaGetSymbolAddress((void**)&scores, g_scores);
    cudaGetSymbolAddress((void**)&lnh,    g_lnh);
    cudaGetSymbolAddress((void**)&lnl,    g_lnl);
    cudaGetSymbolAddress((void**)&qkvh,   g_qkvh);
    cudaGetSymbolAddress((void**)&qkvl,   g_qkvl);
    cudaGetSymbolAddress((void**)&attnh,  g_attnh);
    cudaGetSymbolAddress((void**)&attnl,  g_attnl);
    cudaGetSymbolAddress((void**)&midh,   g_midh);
    cudaGetSymbolAddress((void**)&midl,   g_midl);
    cudaGetSymbolAddress((void**)&wqkvh,  g_wqkvh);
    cudaGetSymbolAddress((void**)&wqkvl,  g_wqkvl);
    cudaGetSymbolAddress((void**)&waph,   g_waph);
    cudaGetSymbolAddress((void**)&wapl,   g_wapl);
    cudaGetSymbolAddress((void**)&wfch,   g_wfch);
    cudaGetSymbolAddress((void**)&wfcl,   g_wfcl);
    cudaGetSymbolAddress((void**)&wmph,   g_wmph);
    cudaGetSymbolAddress((void**)&wmpl,   g_wmpl);
    cudaGetSymbolAddress((void**)&wteh,   g_wteh);
    cudaGetSymbolAddress((void**)&wtel,   g_wtel);

    const int D = DMODEL;
    const int SMEM = 2 * 4 * TILE_E * (int)sizeof(bf16);  // 81920

    cudaFuncSetAttribute(bgemm_kernel,
                         cudaFuncAttributeMaxDynamicSharedMemorySize, SMEM);

    // ---- weight prep (once per call) ----
    {
        dim3 b32(32, 8);
        tsplit_kernel<<<dim3(D / 32, 3 * D / 32, NLAYER), b32>>>(attn_w,  wqkvh, wqkvl, D, 3 * D);
        tsplit_kernel<<<dim3(D / 32, D / 32, NLAYER),     b32>>>(aproj_w, waph,  wapl,  D, D);
        tsplit_kernel<<<dim3(D / 32, 4 * D / 32, NLAYER), b32>>>(fc_w,    wfch,  wfcl,  D, 4 * D);
        tsplit_kernel<<<dim3(4 * D / 32, D / 32, NLAYER), b32>>>(mproj_w, wmph,  wmpl,  4 * D, D);
        long nwte = (long)NVOCAB * D;
        split_kernel<<<(unsigned)((nwte + 255) / 256), 256>>>(wte, wteh, wtel, nwte);
    }

    embed_kernel<<<NTOK, 256>>>(tok, wte, wpe, x);

    for (int l = 0; l < NLAYER; l++) {
        layernorm_kernel<<<NTOK, 256>>>(x, ln1_w + l * D, ln1_b + l * D, lnh, lnl);

        // qkv = h @ attn_w[l] + attn_b[l]  -> fp32 + hi/lo
        {
            dim3 g(3 * D / 128, NTOK / 128);
            bgemm_kernel<<<g, 256, SMEM>>>(
                lnh, lnl, D, 0, 0,
                wqkvh + (long)l * 3 * D * D, wqkvl + (long)l * 3 * D * D, D, 0, 0,
                qkv, qkvh, qkvl, 3 * D, 0, 0,
                attn_b + (long)l * 3 * D,
                NTOK, 3 * D, D, 1, 8 | 16);
        }

        // scores[z] = Q_z @ K_z^T  (causal skip)
        {
            dim3 g(NSEQ / 128, NSEQ / 128, 2 * NHEAD);
            bgemm_kernel<<<g, 256, SMEM>>>(
                qkvh, qkvl,     3 * D, (long)NSEQ * 3 * D, HDIM,
                qkvh + D, qkvl + D, 3 * D, (long)NSEQ * 3 * D, HDIM,
                scores, nullptr, nullptr, NSEQ,
                (long)NHEAD * NSEQ * NSEQ, (long)NSEQ * NSEQ,
                nullptr,
                NSEQ, NSEQ, HDIM, NHEAD, 4 | 8);
        }

        softmax_kernel<<<dim3(NSEQ, 2 * NHEAD), 256>>>(scores);

        // attn[z] = P_z @ V_z (fp32, causal-truncated) -> hi/lo
        {
            dim3 g(1, NSEQ / 64, 2 * NHEAD);
            gemm64_kernel<<<g, 256>>>(
                scores, NSEQ, (long)NHEAD * NSEQ * NSEQ, (long)NSEQ * NSEQ,
                qkv + 2 * D, 3 * D, (long)NSEQ * 3 * D, HDIM,
                attnh, attnl, D, (long)NSEQ * D, HDIM,
                NSEQ, HDIM, NSEQ, NHEAD);
        }

        // x += attn @ aproj_w[l] + aproj_b[l]
        {
            dim3 g(D / 128, NTOK / 128);
            bgemm_kernel<<<g, 256, SMEM>>>(
                attnh, attnl, D, 0, 0,
                waph + (long)l * D * D, wapl + (long)l * D * D, D, 0, 0,
                x, nullptr, nullptr, D, 0, 0,
                aproj_b + (long)l * D,
                NTOK, D, D, 1, 1 | 8);
        }

        layernorm_kernel<<<NTOK, 256>>>(x, ln2_w + l * D, ln2_b + l * D, lnh, lnl);

        // mid = gelu(h @ fc_w[l] + fc_b[l]) -> hi/lo only
        {
            dim3 g(4 * D / 128, NTOK / 128);
            bgemm_kernel<<<g, 256, SMEM>>>(
                lnh, lnl, D, 0, 0,
                wfch + (long)l * 4 * D * D, wfcl + (long)l * 4 * D * D, D, 0, 0,
                nullptr, midh, midl, 4 * D, 0, 0,
                fc_b + (long)l * 4 * D,
                NTOK, 4 * D, D, 1, 2 | 16);
        }

        // x += mid @ mproj_w[l] + mproj_b[l]
        {
            dim3 g(D / 128, NTOK / 128);
            bgemm_kernel<<<g, 256, SMEM>>>(
                midh, midl, 4 * D, 0, 0,
                wmph + (long)l * D * 4 * D, wmpl + (long)l * D * 4 * D, 4 * D, 0, 0,
                x, nullptr, nullptr, D, 0, 0,
                mproj_b + (long)l * D,
                NTOK, D, 4 * D, 1, 1 | 8);
        }
    }

    // final LN + tied lm_head: out = LN_f(x) @ wte^T
    layernorm_kernel<<<NTOK, 256>>>(x, lnf_w, lnf_b, lnh, lnl);
    {
        dim3 g((NVOCAB + 127) / 128, NTOK / 128);
        bgemm_kernel<<<g, 256, SMEM>>>(
            lnh, lnl, D, 0, 0,
            wteh, wtel, D, 0, 0,
            out, nullptr, nullptr, NVOCAB, 0, 0,
            nullptr,
            NTOK, NVOCAB, D, 1, 8);
    }
}

// round 6
// speedup vs baseline: 3.3474x; 1.2894x over previous
#include <cuda_runtime.h>
#include <cuda_bf16.h>
#include <math.h>
#include <stdint.h>

// Problem constants
#define DMODEL 768
#define NTOK   2048          // B*N = 2*1024
#define NSEQ   1024
#define NHEAD  12
#define HDIM   64
#define NLAYER 12
#define NVOCAB 50257

#define KS 40                 // gemm smem k-stride in bf16 elems (conflict-free)
#define TILE_E (128 * KS)     // elems per smem tile array
#define KSQ 72                // flash Q/K smem stride (64+8)
#define KSV 136               // flash V^T smem stride (128+8)

typedef __nv_bfloat16 bf16;

// ---------------------------------------------------------------------------
// Device-global scratch (allocation-free)
// ---------------------------------------------------------------------------
__device__ float g_x[NTOK * DMODEL];                  // residual stream (fp32)

// activations, bf16 hi/lo
__device__ bf16 g_lnh[NTOK * DMODEL],      g_lnl[NTOK * DMODEL];
__device__ bf16 g_qkvh[NTOK * 3 * DMODEL], g_qkvl[NTOK * 3 * DMODEL];
__device__ bf16 g_attnh[NTOK * DMODEL],    g_attnl[NTOK * DMODEL];
__device__ bf16 g_midh[NTOK * 4 * DMODEL], g_midl[NTOK * 4 * DMODEL];

// weights, transposed to [N,K], bf16 hi/lo
__device__ bf16 g_wqkvh[NLAYER * 3 * DMODEL * DMODEL], g_wqkvl[NLAYER * 3 * DMODEL * DMODEL];
__device__ bf16 g_waph [NLAYER * DMODEL * DMODEL],     g_wapl [NLAYER * DMODEL * DMODEL];
__device__ bf16 g_wfch [NLAYER * 4 * DMODEL * DMODEL], g_wfcl [NLAYER * 4 * DMODEL * DMODEL];
__device__ bf16 g_wmph [NLAYER * DMODEL * 4 * DMODEL], g_wmpl [NLAYER * DMODEL * 4 * DMODEL];
__device__ bf16 g_wteh [(long)NVOCAB * DMODEL],        g_wtel [(long)NVOCAB * DMODEL];

// ---------------------------------------------------------------------------
// Helpers
// ---------------------------------------------------------------------------
__device__ __forceinline__ float blockReduceSum(float v) {
    __shared__ float sh[8];
    int lane = threadIdx.x & 31, w = threadIdx.x >> 5;
#pragma unroll
    for (int o = 16; o; o >>= 1) v += __shfl_xor_sync(0xffffffffu, v, o);
    __syncthreads();
    if (lane == 0) sh[w] = v;
    __syncthreads();
    if (threadIdx.x == 0) {
        float s = sh[0];
#pragma unroll
        for (int i = 1; i < 8; i++) s += sh[i];
        sh[0] = s;
    }
    __syncthreads();
    return sh[0];
}

__device__ __forceinline__ void cp16(uint32_t saddr, const void* gaddr) {
    asm volatile("cp.async.cg.shared.global [%0], [%1], 16;\n"
                 :: "r"(saddr), "l"(gaddr));
}

__device__ __forceinline__ void mma16816(float* d, const uint32_t* a, const uint32_t* b) {
    asm volatile(
        "mma.sync.aligned.m16n8k16.row.col.f32.bf16.bf16.f32 "
        "{%0,%1,%2,%3},{%4,%5,%6,%7},{%8,%9},{%0,%1,%2,%3};\n"
        : "+f"(d[0]), "+f"(d[1]), "+f"(d[2]), "+f"(d[3])
        : "r"(a[0]), "r"(a[1]), "r"(a[2]), "r"(a[3]), "r"(b[0]), "r"(b[1]));
}

__device__ __forceinline__ void ldm4(uint32_t* r, uint32_t addr) {
    asm volatile("ldmatrix.sync.aligned.m8n8.x4.shared.b16 {%0,%1,%2,%3}, [%4];\n"
                 : "=r"(r[0]), "=r"(r[1]), "=r"(r[2]), "=r"(r[3]) : "r"(addr));
}

__device__ __forceinline__ uint32_t pack2(float lo, float hi) {
    __nv_bfloat162 t = __float22bfloat162_rn(make_float2(lo, hi));
    return *(uint32_t*)&t;
}
__device__ __forceinline__ uint32_t packlo2(float a, float b) {
    float la = a - __bfloat162float(__float2bfloat16(a));
    float lb = b - __bfloat162float(__float2bfloat16(b));
    return pack2(la, lb);
}

// ---------------------------------------------------------------------------
// Weight prep: transpose+split W[z][K][N] -> T[z][N][K] hi/lo bf16
// ---------------------------------------------------------------------------
__global__ void tsplit_kernel(const float* __restrict__ W,
                              bf16* __restrict__ Th, bf16* __restrict__ Tl,
                              int K, int N) {
    __shared__ float t[32][33];
    long zoff = (long)blockIdx.z * K * N;
    W += zoff; Th += zoff; Tl += zoff;
    int k0 = blockIdx.x * 32, n0 = blockIdx.y * 32;
    int tx = threadIdx.x, ty = threadIdx.y;
#pragma unroll
    for (int i = 0; i < 4; i++)
        t[ty + i * 8][tx] = W[(long)(k0 + ty + i * 8) * N + n0 + tx];
    __syncthreads();
#pragma unroll
    for (int i = 0; i < 4; i++) {
        int n = n0 + ty + i * 8, k = k0 + tx;
        float v = t[tx][ty + i * 8];
        bf16 h = __float2bfloat16(v);
        Th[(long)n * K + k] = h;
        Tl[(long)n * K + k] = __float2bfloat16(v - __bfloat162float(h));
    }
}

__global__ void split_kernel(const float* __restrict__ in,
                             bf16* __restrict__ h, bf16* __restrict__ l, long n) {
    long i = (long)blockIdx.x * 256 + threadIdx.x;
    if (i < n) {
        float v = in[i];
        bf16 hi = __float2bfloat16(v);
        h[i] = hi;
        l[i] = __float2bfloat16(v - __bfloat162float(hi));
    }
}

// ---------------------------------------------------------------------------
// Embedding
// ---------------------------------------------------------------------------
__global__ void embed_kernel(const int* __restrict__ tok,
                             const float* __restrict__ wte,
                             const float* __restrict__ wpe,
                             float* __restrict__ x) {
    int t = blockIdx.x;
    int n = t & (NSEQ - 1);
    int id = tok[t];
    const float* w1 = wte + (long)id * DMODEL;
    const float* w2 = wpe + (long)n * DMODEL;
    float* xo = x + (long)t * DMODEL;
    for (int d = threadIdx.x; d < DMODEL; d += blockDim.x)
        xo[d] = w1[d] + w2[d];
}

// ---------------------------------------------------------------------------
// LayerNorm: fp32 in -> bf16 hi/lo out
// ---------------------------------------------------------------------------
__global__ __launch_bounds__(256) void layernorm_kernel(
    const float* __restrict__ x, const float* __restrict__ w,
    const float* __restrict__ b,
    bf16* __restrict__ oh, bf16* __restrict__ ol) {
    int t = blockIdx.x;
    const float* xr = x + (long)t * DMODEL;
    int tid = threadIdx.x;

    float lx[3];
    float s = 0.f;
#pragma unroll
    for (int i = 0; i < 3; i++) { lx[i] = xr[tid + i * 256]; s += lx[i]; }
    s = blockReduceSum(s);
    float mu = s * (1.f / 768.f);

    float var = 0.f;
#pragma unroll
    for (int i = 0; i < 3; i++) { float d = lx[i] - mu; var += d * d; }
    var = blockReduceSum(var);
    float rstd = rsqrtf(var * (1.f / 768.f) + 1e-5f);

#pragma unroll
    for (int i = 0; i < 3; i++) {
        int d = tid + i * 256;
        float v = (lx[i] - mu) * rstd * w[d] + b[d];
        bf16 h = __float2bfloat16(v);
        oh[(long)t * DMODEL + d] = h;
        ol[(long)t * DMODEL + d] = __float2bfloat16(v - __bfloat162float(h));
    }
}

// ---------------------------------------------------------------------------
// Flash attention: one block per (q-tile of 128 rows, head z).
// 8 warps, each owns 16 q-rows. QK^T and PV use 3-MMA hi/lo bf16.
// Online softmax in fp32 registers. Output -> attnh/attnl (bf16 hi/lo).
// ---------------------------------------------------------------------------
__global__ __launch_bounds__(256) void flash_kernel(
    const bf16* __restrict__ qkvh, const bf16* __restrict__ qkvl,
    bf16* __restrict__ attnh, bf16* __restrict__ attnl) {

    int qi = blockIdx.x;          // q tile 0..7
    int z = blockIdx.y;           // b*NHEAD + h
    int b = z / NHEAD, h = z - b * NHEAD;
    const int rs = 3 * DMODEL;
    long base = (long)b * NSEQ * rs + h * HDIM;

    extern __shared__ bf16 SM[];
    // layout: Qh[128*KSQ] Ql Kh Kl | VTh[64*KSV] VTl
    uint32_t u0 = (uint32_t)__cvta_generic_to_shared(SM);
    const uint32_t uQh = u0;
    const uint32_t uQl = uQh + 128 * KSQ * 2;
    const uint32_t uKh = uQl + 128 * KSQ * 2;
    const uint32_t uKl = uKh + 128 * KSQ * 2;
    const uint32_t uVh = uKl + 128 * KSQ * 2;
    const uint32_t uVl = uVh + 64 * KSV * 2;
    bf16* sVh = SM + 4 * 128 * KSQ;
    bf16* sVl = sVh + 64 * KSV;

    int tid = threadIdx.x, lane = tid & 31, wq = tid >> 5;
    int fr = lane >> 2, fc = lane & 3;

    // ---- load Q tile (cp.async, hi/lo) ----
    {
        int r = tid >> 1, c0 = (tid & 1) * 32;
        const bf16* g = qkvh + base + (long)(qi * 128 + r) * rs + c0;
        uint32_t s = uQh + (r * KSQ + c0) * 2;
        cp16(s, g); cp16(s + 16, g + 8); cp16(s + 32, g + 16); cp16(s + 48, g + 24);
        g = qkvl + base + (long)(qi * 128 + r) * rs + c0;
        s = uQl + (r * KSQ + c0) * 2;
        cp16(s, g); cp16(s + 16, g + 8); cp16(s + 32, g + 16); cp16(s + 48, g + 24);
        asm volatile("cp.async.commit_group;\n" ::: "memory");
    }

    float m0 = -1e30f, m1 = -1e30f, l0 = 0.f, l1 = 0.f;
    float o[8][4] = {};

    for (int kt = 0; kt <= qi; kt++) {
        __syncthreads();   // previous iteration's smem consumers done

        // ---- load K tile (cp.async hi/lo) ----
        {
            int r = tid >> 1, c0 = (tid & 1) * 32;
            const bf16* g = qkvh + base + DMODEL + (long)(kt * 128 + r) * rs + c0;
            uint32_t s = uKh + (r * KSQ + c0) * 2;
            cp16(s, g); cp16(s + 16, g + 8); cp16(s + 32, g + 16); cp16(s + 48, g + 24);
            g = qkvl + base + DMODEL + (long)(kt * 128 + r) * rs + c0;
            s = uKl + (r * KSQ + c0) * 2;
            cp16(s, g); cp16(s + 16, g + 8); cp16(s + 32, g + 16); cp16(s + 48, g + 24);
            asm volatile("cp.async.commit_group;\n" ::: "memory");
        }
        // ---- load V^T (sync, transposed scatter) ----
        {
            int t = tid >> 1, c0 = (tid & 1) * 32;
            const bf16* g = qkvh + base + 2 * DMODEL + (long)(kt * 128 + t) * rs + c0;
            union { uint4 u[4]; bf16 e[32]; } vb;
            vb.u[0] = ((const uint4*)g)[0]; vb.u[1] = ((const uint4*)g)[1];
            vb.u[2] = ((const uint4*)g)[2]; vb.u[3] = ((const uint4*)g)[3];
#pragma unroll
            for (int j = 0; j < 32; j++) sVh[(c0 + j) * KSV + t] = vb.e[j];
            g = qkvl + base + 2 * DMODEL + (long)(kt * 128 + t) * rs + c0;
            vb.u[0] = ((const uint4*)g)[0]; vb.u[1] = ((const uint4*)g)[1];
            vb.u[2] = ((const uint4*)g)[2]; vb.u[3] = ((const uint4*)g)[3];
#pragma unroll
            for (int j = 0; j < 32; j++) sVl[(c0 + j) * KSV + t] = vb.e[j];
        }
        asm volatile("cp.async.wait_group 0;\n" ::: "memory");
        __syncthreads();

        // ---- S = Q @ K^T (3-MMA hi/lo), warp rows wq*16..+15, cols 0..127 ----
        float ss[16][4];
#pragma unroll
        for (int i = 0; i < 16; i++)
#pragma unroll
            for (int r = 0; r < 4; r++) ss[i][r] = 0.f;

#pragma unroll
        for (int ks4 = 0; ks4 < 4; ks4++) {
            int ks = ks4 * 16;
            uint32_t ah[4], al[4];
            uint32_t aoff = ((wq * 16 + (lane & 15)) * KSQ + ks + ((lane >> 4) << 3)) * 2;
            ldm4(ah, uQh + aoff);
            ldm4(al, uQl + aoff);
#pragma unroll
            for (int nip = 0; nip < 8; nip++) {
                uint32_t bh[4], bl[4];
                uint32_t boff = ((nip * 16 + ((lane >> 4) << 3) + (lane & 7)) * KSQ
                                 + ks + (((lane >> 3) & 1) << 3)) * 2;
                ldm4(bh, uKh + boff);
                ldm4(bl, uKl + boff);
                int ni = nip * 2;
                mma16816(ss[ni], ah, bh);     mma16816(ss[ni + 1], ah, bh + 2);
                mma16816(ss[ni], al, bh);     mma16816(ss[ni + 1], al, bh + 2);
                mma16816(ss[ni], ah, bl);     mma16816(ss[ni + 1], ah, bl + 2);
            }
        }

        // ---- scale + causal mask ----
#pragma unroll
        for (int i = 0; i < 16; i++)
#pragma unroll
            for (int r = 0; r < 4; r++) ss[i][r] *= 0.125f;
        if (kt == qi) {
#pragma unroll
            for (int i = 0; i < 16; i++)
#pragma unroll
                for (int r = 0; r < 4; r++) {
                    int col = i * 8 + fc * 2 + (r & 1);
                    int row = wq * 16 + fr + ((r >> 1) << 3);
                    if (col > row) ss[i][r] = -1e30f;
                }
        }

        // ---- online softmax (rows fr / fr+8 per thread) ----
        float mx0 = -1e30f, mx1 = -1e30f;
#pragma unroll
        for (int i = 0; i < 16; i++) {
            mx0 = fmaxf(mx0, fmaxf(ss[i][0], ss[i][1]));
            mx1 = fmaxf(mx1, fmaxf(ss[i][2], ss[i][3]));
        }
        mx0 = fmaxf(mx0, __shfl_xor_sync(0xffffffffu, mx0, 1));
        mx0 = fmaxf(mx0, __shfl_xor_sync(0xffffffffu, mx0, 2));
        mx1 = fmaxf(mx1, __shfl_xor_sync(0xffffffffu, mx1, 1));
        mx1 = fmaxf(mx1, __shfl_xor_sync(0xffffffffu, mx1, 2));

        float mn0 = fmaxf(m0, mx0), mn1 = fmaxf(m1, mx1);
        float al0 = __expf(m0 - mn0), al1 = __expf(m1 - mn1);
        float sum0 = 0.f, sum1 = 0.f;
#pragma unroll
        for (int i = 0; i < 16; i++) {
            ss[i][0] = __expf(ss[i][0] - mn0); sum0 += ss[i][0];
            ss[i][1] = __expf(ss[i][1] - mn0); sum0 += ss[i][1];
            ss[i][2] = __expf(ss[i][2] - mn1); sum1 += ss[i][2];
            ss[i][3] = __expf(ss[i][3] - mn1); sum1 += ss[i][3];
        }
        sum0 += __shfl_xor_sync(0xffffffffu, sum0, 1);
        sum0 += __shfl_xor_sync(0xffffffffu, sum0, 2);
        sum1 += __shfl_xor_sync(0xffffffffu, sum1, 1);
        sum1 += __shfl_xor_sync(0xffffffffu, sum1, 2);
        l0 = l0 * al0 + sum0;
        l1 = l1 * al1 + sum1;
        m0 = mn0; m1 = mn1;
#pragma unroll
        for (int v = 0; v < 8; v++) {
            o[v][0] *= al0; o[v][1] *= al0;
            o[v][2] *= al1; o[v][3] *= al1;
        }

        // ---- O += P @ V  (P hi/lo from regs, V^T hi/lo from smem) ----
#pragma unroll
        for (int ks = 0; ks < 8; ks++) {
            uint32_t ahi[4], alo[4];
            ahi[0] = pack2(ss[2 * ks][0], ss[2 * ks][1]);
            ahi[1] = pack2(ss[2 * ks][2], ss[2 * ks][3]);
            ahi[2] = pack2(ss[2 * ks + 1][0], ss[2 * ks + 1][1]);
            ahi[3] = pack2(ss[2 * ks + 1][2], ss[2 * ks + 1][3]);
            alo[0] = packlo2(ss[2 * ks][0], ss[2 * ks][1]);
            alo[1] = packlo2(ss[2 * ks][2], ss[2 * ks][3]);
            alo[2] = packlo2(ss[2 * ks + 1][0], ss[2 * ks + 1][1]);
            alo[3] = packlo2(ss[2 * ks + 1][2], ss[2 * ks + 1][3]);
#pragma unroll
            for (int nvp = 0; nvp < 4; nvp++) {
                uint32_t bv[4], bvl[4];
                uint32_t boff = ((nvp * 16 + ((lane >> 4) << 3) + (lane & 7)) * KSV
                                 + ks * 16 + (((lane >> 3) & 1) << 3)) * 2;
                ldm4(bv, uVh + boff);
                ldm4(bvl, uVl + boff);
                int nv = nvp * 2;
                mma16816(o[nv], ahi, bv);     mma16816(o[nv + 1], ahi, bv + 2);
                mma16816(o[nv], alo, bv);     mma16816(o[nv + 1], alo, bv + 2);
                mma16816(o[nv], ahi, bvl);    mma16816(o[nv + 1], ahi, bvl + 2);
            }
        }
    }

    // ---- epilogue: O /= l, write bf16 hi/lo ----
    float inv0 = 1.f / l0, inv1 = 1.f / l1;
    int row0 = qi * 128 + wq * 16 + fr;
#pragma unroll
    for (int v = 0; v < 8; v++) {
#pragma unroll
        for (int r = 0; r < 4; r++) {
            int row = row0 + ((r >> 1) << 3);
            int col = h * HDIM + v * 8 + fc * 2 + (r & 1);
            float val = o[v][r] * ((r >> 1) ? inv1 : inv0);
            long gi = (long)(b * NSEQ + row) * DMODEL + col;
            bf16 hh = __float2bfloat16(val);
            attnh[gi] = hh;
            attnl[gi] = __float2bfloat16(val - __bfloat162float(hh));
        }
    }
}

// ---------------------------------------------------------------------------
// Tensor-core GEMM, 3-MMA bf16 hi/lo, ldmatrix fragment loads.
//   A: [M,K] hi/lo, stride lda.  B: [N,K] hi/lo, stride ldb.
//   128x128 tile, BK=32, 8 warps (2m x 4n). flags: 1=residual, 2=GELU,
//   8=write fp32 C, 16=write bf16 hi/lo.
// ---------------------------------------------------------------------------
__global__ __launch_bounds__(256, 2) void bgemm_kernel(
    const bf16* __restrict__ Ah, const bf16* __restrict__ Al, int lda,
    const bf16* __restrict__ Bh, const bf16* __restrict__ Bl, int ldb,
    float* __restrict__ C, bf16* __restrict__ Ch, bf16* __restrict__ Cl, int ldc,
    const float* __restrict__ bias,
    int M, int N, int K, int flags) {

    int m0 = blockIdx.y * 128, n0 = blockIdx.x * 128;

    extern __shared__ bf16 S[];   // [2 bufs][Ah,Al,Bh,Bl][TILE_E]
    uint32_t sbase = (uint32_t)__cvta_generic_to_shared(S);

    int tid = threadIdx.x, lane = tid & 31, wid = tid >> 5;
    int wm = wid & 1, wn = wid >> 1;
    int fr = lane >> 2, fc = lane & 3;

    int r2 = tid >> 1;
    int c2 = (tid & 1) * 16;

    float acc[4][4][4];
#pragma unroll
    for (int i = 0; i < 4; i++)
#pragma unroll
        for (int j = 0; j < 4; j++)
#pragma unroll
            for (int r = 0; r < 4; r++) acc[i][j][r] = 0.f;

    auto ldStage = [&](int k0, int bufi) {
        uint32_t sb = sbase + bufi * (4 * TILE_E * 2);
        uint32_t sa = sb + r2 * (KS * 2) + c2 * 2;
        const bf16* ga = Ah + (long)(m0 + r2) * lda + k0 + c2;
        cp16(sa, ga);            cp16(sa + 16, ga + 8);
        ga = Al + (long)(m0 + r2) * lda + k0 + c2;
        cp16(sa + TILE_E * 2, ga); cp16(sa + TILE_E * 2 + 16, ga + 8);
        int gn = n0 + r2;
        uint32_t sbB = sb + 2 * TILE_E * 2 + r2 * (KS * 2) + c2 * 2;
        if (gn < N) {
            const bf16* gb = Bh + (long)gn * ldb + k0 + c2;
            cp16(sbB, gb);            cp16(sbB + 16, gb + 8);
            gb = Bl + (long)gn * ldb + k0 + c2;
            cp16(sbB + TILE_E * 2, gb); cp16(sbB + TILE_E * 2 + 16, gb + 8);
        } else {
            uint4 zz = make_uint4(0, 0, 0, 0);
            bf16* p = S + bufi * 4 * TILE_E + 2 * TILE_E + r2 * KS + c2;
            *(uint4*)p = zz; *(uint4*)(p + 8) = zz;
            p += TILE_E;
            *(uint4*)p = zz; *(uint4*)(p + 8) = zz;
        }
        asm volatile("cp.async.commit_group;\n" ::: "memory");
    };

    ldStage(0, 0);

    // per-thread ldmatrix address components (elem offsets)
    int aRow = wm * 64 + (lane & 15);
    int aColX = (lane >> 4) << 3;
    int bRow = wn * 32 + ((lane >> 4) << 3) + (lane & 7);
    int bColX = ((lane >> 3) & 1) << 3;

    int KT = K >> 5;
    int buf = 0;
    for (int kt = 0; kt < KT; kt++) {
        asm volatile("cp.async.wait_group 0;\n" ::: "memory");
        __syncthreads();
        if (kt + 1 < KT) ldStage((kt + 1) << 5, buf ^ 1);

        uint32_t sb = sbase + buf * (4 * TILE_E * 2);

#pragma unroll
        for (int ks = 0; ks < 32; ks += 16) {
            uint32_t ah[4][4], al[4][4], bh[4][2], bl[4][2];
            uint32_t aA = sb + (aRow * KS + ks + aColX) * 2;
#pragma unroll
            for (int mi = 0; mi < 4; mi++) {
                ldm4(ah[mi], aA + mi * (16 * KS * 2));
                ldm4(al[mi], aA + mi * (16 * KS * 2) + TILE_E * 2);
            }
            uint32_t bB = sb + 2 * TILE_E * 2 + (bRow * KS + ks + bColX) * 2;
#pragma unroll
            for (int nip = 0; nip < 2; nip++) {
                ldm4(&bh[nip * 2][0], bB + nip * (16 * KS * 2));
                ldm4(&bl[nip * 2][0], bB + nip * (16 * KS * 2) + TILE_E * 2);
            }
#pragma unroll
            for (int mi = 0; mi < 4; mi++)
#pragma unroll
                for (int ni = 0; ni < 4; ni++)
                    mma16816(acc[mi][ni], ah[mi], bh[ni]);
#pragma unroll
            for (int mi = 0; mi < 4; mi++)
#pragma unroll
                for (int ni = 0; ni < 4; ni++)
                    mma16816(acc[mi][ni], al[mi], bh[ni]);
#pragma unroll
            for (int ni = 0; ni < 4; ni++)
#pragma unroll
                for (int mi = 0; mi < 4; mi++)
                    mma16816(acc[mi][ni], ah[mi], bl[ni]);
        }
        __syncthreads();
        buf ^= 1;
    }

    // Epilogue
#pragma unroll
    for (int mi = 0; mi < 4; mi++) {
        int gm0 = m0 + wm * 64 + mi * 16 + fr;
#pragma unroll
        for (int ni = 0; ni < 4; ni++) {
            int gn = n0 + wn * 32 + ni * 8 + fc * 2;
#pragma unroll
            for (int r = 0; r < 4; r++) {
                int gm = gm0 + (r >= 2 ? 8 : 0);
                int gc = gn + (r & 1);
                if (gc < N) {
                    float v = acc[mi][ni][r];
                    if (bias) v += bias[gc];
                    if (flags & 2) v = 0.5f * v * (1.f + erff(v * 0.70710678118654752f));
                    long idx = (long)gm * ldc + gc;
                    if (flags & 1) v += C[idx];
                    if (flags & 8) C[idx] = v;
                    if (flags & 16) {
                        bf16 h = __float2bfloat16(v);
                        Ch[idx] = h;
                        Cl[idx] = __float2bfloat16(v - __bfloat162float(h));
                    }
                }
            }
        }
    }
}

// ---------------------------------------------------------------------------
// Host-side orchestration
// ---------------------------------------------------------------------------
extern "C" void kernel_launch(void* const* d_in, const int* in_sizes, int n_in,
                              void* d_out, int out_size) {
    (void)in_sizes; (void)n_in; (void)out_size;

    const int*   tok     = (const int*)  d_in[0];
    const float* wte     = (const float*)d_in[1];
    const float* wpe     = (const float*)d_in[2];
    const float* ln1_w   = (const float*)d_in[3];
    const float* ln1_b   = (const float*)d_in[4];
    const float* attn_w  = (const float*)d_in[5];
    const float* attn_b  = (const float*)d_in[6];
    const float* aproj_w = (const float*)d_in[7];
    const float* aproj_b = (const float*)d_in[8];
    const float* ln2_w   = (const float*)d_in[9];
    const float* ln2_b   = (const float*)d_in[10];
    const float* fc_w    = (const float*)d_in[11];
    const float* fc_b    = (const float*)d_in[12];
    const float* mproj_w = (const float*)d_in[13];
    const float* mproj_b = (const float*)d_in[14];
    const float* lnf_w   = (const float*)d_in[15];
    const float* lnf_b   = (const float*)d_in[16];
    float* out = (float*)d_out;

    float *x;
    bf16 *lnh, *lnl, *qkvh, *qkvl, *attnh, *attnl, *midh, *midl;
    bf16 *wqkvh, *wqkvl, *waph, *wapl, *wfch, *wfcl, *wmph, *wmpl, *wteh, *wtel;
    cudaGetSymbolAddress((void**)&x,      g_x);
    cudaGetSymbolAddress((void**)&lnh,    g_lnh);
    cudaGetSymbolAddress((void**)&lnl,    g_lnl);
    cudaGetSymbolAddress((void**)&qkvh,   g_qkvh);
    cudaGetSymbolAddress((void**)&qkvl,   g_qkvl);
    cudaGetSymbolAddress((void**)&attnh,  g_attnh);
    cudaGetSymbolAddress((void**)&attnl,  g_attnl);
    cudaGetSymbolAddress((void**)&midh,   g_midh);
    cudaGetSymbolAddress((void**)&midl,   g_midl);
    cudaGetSymbolAddress((void**)&wqkvh,  g_wqkvh);
    cudaGetSymbolAddress((void**)&wqkvl,  g_wqkvl);
    cudaGetSymbolAddress((void**)&waph,   g_waph);
    cudaGetSymbolAddress((void**)&wapl,   g_wapl);
    cudaGetSymbolAddress((void**)&wfch,   g_wfch);
    cudaGetSymbolAddress((void**)&wfcl,   g_wfcl);
    cudaGetSymbolAddress((void**)&wmph,   g_wmph);
    cudaGetSymbolAddress((void**)&wmpl,   g_wmpl);
    cudaGetSymbolAddress((void**)&wteh,   g_wteh);
    cudaGetSymbolAddress((void**)&wtel,   g_wtel);

    const int D = DMODEL;
    const int SMEM = 2 * 4 * TILE_E * (int)sizeof(bf16);               // 81920
    const int FSMEM = (4 * 128 * KSQ + 2 * 64 * KSV) * (int)sizeof(bf16); // 108544

    cudaFuncSetAttribute(bgemm_kernel,
                         cudaFuncAttributeMaxDynamicSharedMemorySize, SMEM);
    cudaFuncSetAttribute(flash_kernel,
                         cudaFuncAttributeMaxDynamicSharedMemorySize, FSMEM);

    // ---- weight prep (once per call) ----
    {
        dim3 b32(32, 8);
        tsplit_kernel<<<dim3(D / 32, 3 * D / 32, NLAYER), b32>>>(attn_w,  wqkvh, wqkvl, D, 3 * D);
        tsplit_kernel<<<dim3(D / 32, D / 32, NLAYER),     b32>>>(aproj_w, waph,  wapl,  D, D);
        tsplit_kernel<<<dim3(D / 32, 4 * D / 32, NLAYER), b32>>>(fc_w,    wfch,  wfcl,  D, 4 * D);
        tsplit_kernel<<<dim3(4 * D / 32, D / 32, NLAYER), b32>>>(mproj_w, wmph,  wmpl,  4 * D, D);
        long nwte = (long)NVOCAB * D;
        split_kernel<<<(unsigned)((nwte + 255) / 256), 256>>>(wte, wteh, wtel, nwte);
    }

    embed_kernel<<<NTOK, 256>>>(tok, wte, wpe, x);

    for (int l = 0; l < NLAYER; l++) {
        layernorm_kernel<<<NTOK, 256>>>(x, ln1_w + l * D, ln1_b + l * D, lnh, lnl);

        // qkv = h @ attn_w[l] + attn_b[l] -> bf16 hi/lo
        {
            dim3 g(3 * D / 128, NTOK / 128);
            bgemm_kernel<<<g, 256, SMEM>>>(
                lnh, lnl, D,
                wqkvh + (long)l * 3 * D * D, wqkvl + (long)l * 3 * D * D, D,
                nullptr, qkvh, qkvl, 3 * D,
                attn_b + (long)l * 3 * D,
                NTOK, 3 * D, D, 16);
        }

        // fused flash attention -> attnh/attnl
        flash_kernel<<<dim3(NSEQ / 128, 2 * NHEAD), 256, FSMEM>>>(qkvh, qkvl, attnh, attnl);

        // x += attn @ aproj_w[l] + aproj_b[l]
        {
            dim3 g(D / 128, NTOK / 128);
            bgemm_kernel<<<g, 256, SMEM>>>(
                attnh, attnl, D,
                waph + (long)l * D * D, wapl + (long)l * D * D, D,
                x, nullptr, nullptr, D,
                aproj_b + (long)l * D,
                NTOK, D, D, 1 | 8);
        }

        layernorm_kernel<<<NTOK, 256>>>(x, ln2_w + l * D, ln2_b + l * D, lnh, lnl);

        // mid = gelu(h @ fc_w[l] + fc_b[l]) -> hi/lo
        {
            dim3 g(4 * D / 128, NTOK / 128);
            bgemm_kernel<<<g, 256, SMEM>>>(
                lnh, lnl, D,
                wfch + (long)l * 4 * D * D, wfcl + (long)l * 4 * D * D, D,
                nullptr, midh, midl, 4 * D,
                fc_b + (long)l * 4 * D,
                NTOK, 4 * D, D, 2 | 16);
        }

        // x += mid @ mproj_w[l] + mproj_b[l]
        {
            dim3 g(D / 128, NTOK / 128);
            bgemm_kernel<<<g, 256, SMEM>>>(
                midh, midl, 4 * D,
                wmph + (long)l * D * 4 * D, wmpl + (long)l * D * 4 * D, 4 * D,
                x, nullptr, nullptr, D,
                mproj_b + (long)l * D,
                NTOK, D, 4 * D, 1 | 8);
        }
    }

    // final LN + tied lm_head: out = LN_f(x) @ wte^T
    layernorm_kernel<<<NTOK, 256>>>(x, lnf_w, lnf_b, lnh, lnl);
    {
        dim3 g((NVOCAB + 127) / 128, NTOK / 128);
        bgemm_kernel<<<g, 256, SMEM>>>(
            lnh, lnl, D,
            wteh, wtel, D,
            out, nullptr, nullptr, NVOCAB,
            nullptr,
            NTOK, NVOCAB, D, 8);
    }
}

// round 8
// speedup vs baseline: 3.6848x; 1.1008x over previous
#include <cuda_runtime.h>
#include <cuda_bf16.h>
#include <cuda_fp16.h>
#include <math.h>
#include <stdint.h>

// Problem constants
#define DMODEL 768
#define NTOK   2048          // B*N = 2*1024
#define NSEQ   1024
#define NHEAD  12
#define HDIM   64
#define NLAYER 12
#define NVOCAB 50257

#define KS 40                 // gemm smem k-stride in 16-bit elems (conflict-free)
#define TILE_E (128 * KS)     // elems per smem tile array
#define KSQ 72                // flash Q/K smem stride (64+8)
#define KSV 136               // flash V^T smem stride (128+8)

typedef __nv_bfloat16 bf16;

// ---------------------------------------------------------------------------
// Device-global scratch (allocation-free)
// ---------------------------------------------------------------------------
__device__ float g_x[NTOK * DMODEL];                  // residual stream (fp32)

// activations, bf16 hi/lo
__device__ bf16 g_lnh[NTOK * DMODEL],      g_lnl[NTOK * DMODEL];
__device__ bf16 g_qkvh[NTOK * 3 * DMODEL], g_qkvl[NTOK * 3 * DMODEL];
__device__ bf16 g_attnh[NTOK * DMODEL],    g_attnl[NTOK * DMODEL];
__device__ bf16 g_midh[NTOK * 4 * DMODEL], g_midl[NTOK * 4 * DMODEL];

// final-LN output in fp16 (lm_head only)
__device__ __half g_lnf16[NTOK * DMODEL];

// weights, transposed to [N,K], bf16 hi/lo
__device__ bf16 g_wqkvh[NLAYER * 3 * DMODEL * DMODEL], g_wqkvl[NLAYER * 3 * DMODEL * DMODEL];
__device__ bf16 g_waph [NLAYER * DMODEL * DMODEL],     g_wapl [NLAYER * DMODEL * DMODEL];
__device__ bf16 g_wfch [NLAYER * 4 * DMODEL * DMODEL], g_wfcl [NLAYER * 4 * DMODEL * DMODEL];
__device__ bf16 g_wmph [NLAYER * DMODEL * 4 * DMODEL], g_wmpl [NLAYER * DMODEL * 4 * DMODEL];
__device__ __half g_wtef[(long)NVOCAB * DMODEL];      // wte in fp16 (lm_head)

// ---------------------------------------------------------------------------
// Helpers
// ---------------------------------------------------------------------------
__device__ __forceinline__ float blockReduceSum(float v) {
    __shared__ float sh[8];
    int lane = threadIdx.x & 31, w = threadIdx.x >> 5;
#pragma unroll
    for (int o = 16; o; o >>= 1) v += __shfl_xor_sync(0xffffffffu, v, o);
    __syncthreads();
    if (lane == 0) sh[w] = v;
    __syncthreads();
    if (threadIdx.x == 0) {
        float s = sh[0];
#pragma unroll
        for (int i = 1; i < 8; i++) s += sh[i];
        sh[0] = s;
    }
    __syncthreads();
    return sh[0];
}

__device__ __forceinline__ void cp16(uint32_t saddr, const void* gaddr) {
    asm volatile("cp.async.cg.shared.global [%0], [%1], 16;\n"
                 :: "r"(saddr), "l"(gaddr));
}

__device__ __forceinline__ void mma16816(float* d, const uint32_t* a, const uint32_t* b) {
    asm volatile(
        "mma.sync.aligned.m16n8k16.row.col.f32.bf16.bf16.f32 "
        "{%0,%1,%2,%3},{%4,%5,%6,%7},{%8,%9},{%0,%1,%2,%3};\n"
        : "+f"(d[0]), "+f"(d[1]), "+f"(d[2]), "+f"(d[3])
        : "r"(a[0]), "r"(a[1]), "r"(a[2]), "r"(a[3]), "r"(b[0]), "r"(b[1]));
}

__device__ __forceinline__ void mma16816h(float* d, const uint32_t* a, const uint32_t* b) {
    asm volatile(
        "mma.sync.aligned.m16n8k16.row.col.f32.f16.f16.f32 "
        "{%0,%1,%2,%3},{%4,%5,%6,%7},{%8,%9},{%0,%1,%2,%3};\n"
        : "+f"(d[0]), "+f"(d[1]), "+f"(d[2]), "+f"(d[3])
        : "r"(a[0]), "r"(a[1]), "r"(a[2]), "r"(a[3]), "r"(b[0]), "r"(b[1]));
}

__device__ __forceinline__ void ldm4(uint32_t* r, uint32_t addr) {
    asm volatile("ldmatrix.sync.aligned.m8n8.x4.shared.b16 {%0,%1,%2,%3}, [%4];\n"
                 : "=r"(r[0]), "=r"(r[1]), "=r"(r[2]), "=r"(r[3]) : "r"(addr));
}

__device__ __forceinline__ uint32_t pack2(float lo, float hi) {
    __nv_bfloat162 t = __float22bfloat162_rn(make_float2(lo, hi));
    return *(uint32_t*)&t;
}
__device__ __forceinline__ uint32_t packlo2(float a, float b) {
    float la = a - __bfloat162float(__float2bfloat16(a));
    float lb = b - __bfloat162float(__float2bfloat16(b));
    return pack2(la, lb);
}

// ---------------------------------------------------------------------------
// Weight prep: transpose+split W[z][K][N] -> T[z][N][K] hi/lo bf16
// ---------------------------------------------------------------------------
__global__ void tsplit_kernel(const float* __restrict__ W,
                              bf16* __restrict__ Th, bf16* __restrict__ Tl,
                              int K, int N) {
    __shared__ float t[32][33];
    long zoff = (long)blockIdx.z * K * N;
    W += zoff; Th += zoff; Tl += zoff;
    int k0 = blockIdx.x * 32, n0 = blockIdx.y * 32;
    int tx = threadIdx.x, ty = threadIdx.y;
#pragma unroll
    for (int i = 0; i < 4; i++)
        t[ty + i * 8][tx] = W[(long)(k0 + ty + i * 8) * N + n0 + tx];
    __syncthreads();
#pragma unroll
    for (int i = 0; i < 4; i++) {
        int n = n0 + ty + i * 8, k = k0 + tx;
        float v = t[tx][ty + i * 8];
        bf16 h = __float2bfloat16(v);
        Th[(long)n * K + k] = h;
        Tl[(long)n * K + k] = __float2bfloat16(v - __bfloat162float(h));
    }
}

// Elementwise fp32 -> fp16 (wte is already [V, D] = [N, K])
__global__ void splitf16_kernel(const float* __restrict__ in,
                                __half* __restrict__ o, long n) {
    long i = (long)blockIdx.x * 256 + threadIdx.x;
    if (i < n) o[i] = __float2half(in[i]);
}

// ---------------------------------------------------------------------------
// Embedding
// ---------------------------------------------------------------------------
__global__ void embed_kernel(const int* __restrict__ tok,
                             const float* __restrict__ wte,
                             const float* __restrict__ wpe,
                             float* __restrict__ x) {
    int t = blockIdx.x;
    int n = t & (NSEQ - 1);
    int id = tok[t];
    const float* w1 = wte + (long)id * DMODEL;
    const float* w2 = wpe + (long)n * DMODEL;
    float* xo = x + (long)t * DMODEL;
    for (int d = threadIdx.x; d < DMODEL; d += blockDim.x)
        xo[d] = w1[d] + w2[d];
}

// ---------------------------------------------------------------------------
// LayerNorm: fp32 in -> bf16 hi/lo out
// ---------------------------------------------------------------------------
__global__ __launch_bounds__(256) void layernorm_kernel(
    const float* __restrict__ x, const float* __restrict__ w,
    const float* __restrict__ b,
    bf16* __restrict__ oh, bf16* __restrict__ ol) {
    int t = blockIdx.x;
    const float* xr = x + (long)t * DMODEL;
    int tid = threadIdx.x;

    float lx[3];
    float s = 0.f;
#pragma unroll
    for (int i = 0; i < 3; i++) { lx[i] = xr[tid + i * 256]; s += lx[i]; }
    s = blockReduceSum(s);
    float mu = s * (1.f / 768.f);

    float var = 0.f;
#pragma unroll
    for (int i = 0; i < 3; i++) { float d = lx[i] - mu; var += d * d; }
    var = blockReduceSum(var);
    float rstd = rsqrtf(var * (1.f / 768.f) + 1e-5f);

#pragma unroll
    for (int i = 0; i < 3; i++) {
        int d = tid + i * 256;
        float v = (lx[i] - mu) * rstd * w[d] + b[d];
        bf16 h = __float2bfloat16(v);
        oh[(long)t * DMODEL + d] = h;
        ol[(long)t * DMODEL + d] = __float2bfloat16(v - __bfloat162float(h));
    }
}

// LayerNorm: fp32 in -> fp16 out (final LN, feeds fp16 lm_head)
__global__ __launch_bounds__(256) void layernorm_f16_kernel(
    const float* __restrict__ x, const float* __restrict__ w,
    const float* __restrict__ b, __half* __restrict__ o) {
    int t = blockIdx.x;
    const float* xr = x + (long)t * DMODEL;
    int tid = threadIdx.x;

    float lx[3];
    float s = 0.f;
#pragma unroll
    for (int i = 0; i < 3; i++) { lx[i] = xr[tid + i * 256]; s += lx[i]; }
    s = blockReduceSum(s);
    float mu = s * (1.f / 768.f);

    float var = 0.f;
#pragma unroll
    for (int i = 0; i < 3; i++) { float d = lx[i] - mu; var += d * d; }
    var = blockReduceSum(var);
    float rstd = rsqrtf(var * (1.f / 768.f) + 1e-5f);

#pragma unroll
    for (int i = 0; i < 3; i++) {
        int d = tid + i * 256;
        float v = (lx[i] - mu) * rstd * w[d] + b[d];
        o[(long)t * DMODEL + d] = __float2half(v);
    }
}

// ---------------------------------------------------------------------------
// Flash attention (unchanged from round 6): one block per (q-tile, head).
// ---------------------------------------------------------------------------
__global__ __launch_bounds__(256) void flash_kernel(
    const bf16* __restrict__ qkvh, const bf16* __restrict__ qkvl,
    bf16* __restrict__ attnh, bf16* __restrict__ attnl) {

    int qi = blockIdx.x;
    int z = blockIdx.y;
    int b = z / NHEAD, h = z - b * NHEAD;
    const int rs = 3 * DMODEL;
    long base = (long)b * NSEQ * rs + h * HDIM;

    extern __shared__ bf16 SM[];
    uint32_t u0 = (uint32_t)__cvta_generic_to_shared(SM);
    const uint32_t uQh = u0;
    const uint32_t uQl = uQh + 128 * KSQ * 2;
    const uint32_t uKh = uQl + 128 * KSQ * 2;
    const uint32_t uKl = uKh + 128 * KSQ * 2;
    const uint32_t uVh = uKl + 128 * KSQ * 2;
    const uint32_t uVl = uVh + 64 * KSV * 2;
    bf16* sVh = SM + 4 * 128 * KSQ;
    bf16* sVl = sVh + 64 * KSV;

    int tid = threadIdx.x, lane = tid & 31, wq = tid >> 5;
    int fr = lane >> 2, fc = lane & 3;

    {
        int r = tid >> 1, c0 = (tid & 1) * 32;
        const bf16* g = qkvh + base + (long)(qi * 128 + r) * rs + c0;
        uint32_t s = uQh + (r * KSQ + c0) * 2;
        cp16(s, g); cp16(s + 16, g + 8); cp16(s + 32, g + 16); cp16(s + 48, g + 24);
        g = qkvl + base + (long)(qi * 128 + r) * rs + c0;
        s = uQl + (r * KSQ + c0) * 2;
        cp16(s, g); cp16(s + 16, g + 8); cp16(s + 32, g + 16); cp16(s + 48, g + 24);
        asm volatile("cp.async.commit_group;\n" ::: "memory");
    }

    float m0 = -1e30f, m1 = -1e30f, l0 = 0.f, l1 = 0.f;
    float o[8][4] = {};

    for (int kt = 0; kt <= qi; kt++) {
        __syncthreads();

        {
            int r = tid >> 1, c0 = (tid & 1) * 32;
            const bf16* g = qkvh + base + DMODEL + (long)(kt * 128 + r) * rs + c0;
            uint32_t s = uKh + (r * KSQ + c0) * 2;
            cp16(s, g); cp16(s + 16, g + 8); cp16(s + 32, g + 16); cp16(s + 48, g + 24);
            g = qkvl + base + DMODEL + (long)(kt * 128 + r) * rs + c0;
            s = uKl + (r * KSQ + c0) * 2;
            cp16(s, g); cp16(s + 16, g + 8); cp16(s + 32, g + 16); cp16(s + 48, g + 24);
            asm volatile("cp.async.commit_group;\n" ::: "memory");
        }
        {
            int t = tid >> 1, c0 = (tid & 1) * 32;
            const bf16* g = qkvh + base + 2 * DMODEL + (long)(kt * 128 + t) * rs + c0;
            union { uint4 u[4]; bf16 e[32]; } vb;
            vb.u[0] = ((const uint4*)g)[0]; vb.u[1] = ((const uint4*)g)[1];
            vb.u[2] = ((const uint4*)g)[2]; vb.u[3] = ((const uint4*)g)[3];
#pragma unroll
            for (int j = 0; j < 32; j++) sVh[(c0 + j) * KSV + t] = vb.e[j];
            g = qkvl + base + 2 * DMODEL + (long)(kt * 128 + t) * rs + c0;
            vb.u[0] = ((const uint4*)g)[0]; vb.u[1] = ((const uint4*)g)[1];
            vb.u[2] = ((const uint4*)g)[2]; vb.u[3] = ((const uint4*)g)[3];
#pragma unroll
            for (int j = 0; j < 32; j++) sVl[(c0 + j) * KSV + t] = vb.e[j];
        }
        asm volatile("cp.async.wait_group 0;\n" ::: "memory");
        __syncthreads();

        float ss[16][4];
#pragma unroll
        for (int i = 0; i < 16; i++)
#pragma unroll
            for (int r = 0; r < 4; r++) ss[i][r] = 0.f;

#pragma unroll
        for (int ks4 = 0; ks4 < 4; ks4++) {
            int ks = ks4 * 16;
            uint32_t ah[4], al[4];
            uint32_t aoff = ((wq * 16 + (lane & 15)) * KSQ + ks + ((lane >> 4) << 3)) * 2;
            ldm4(ah, uQh + aoff);
            ldm4(al, uQl + aoff);
#pragma unroll
            for (int nip = 0; nip < 8; nip++) {
                uint32_t bh[4], bl[4];
                uint32_t boff = ((nip * 16 + ((lane >> 4) << 3) + (lane & 7)) * KSQ
                                 + ks + (((lane >> 3) & 1) << 3)) * 2;
                ldm4(bh, uKh + boff);
                ldm4(bl, uKl + boff);
                int ni = nip * 2;
                mma16816(ss[ni], ah, bh);     mma16816(ss[ni + 1], ah, bh + 2);
                mma16816(ss[ni], al, bh);     mma16816(ss[ni + 1], al, bh + 2);
                mma16816(ss[ni], ah, bl);     mma16816(ss[ni + 1], ah, bl + 2);
            }
        }

#pragma unroll
        for (int i = 0; i < 16; i++)
#pragma unroll
            for (int r = 0; r < 4; r++) ss[i][r] *= 0.125f;
        if (kt == qi) {
#pragma unroll
            for (int i = 0; i < 16; i++)
#pragma unroll
                for (int r = 0; r < 4; r++) {
                    int col = i * 8 + fc * 2 + (r & 1);
                    int row = wq * 16 + fr + ((r >> 1) << 3);
                    if (col > row) ss[i][r] = -1e30f;
                }
        }

        float mx0 = -1e30f, mx1 = -1e30f;
#pragma unroll
        for (int i = 0; i < 16; i++) {
            mx0 = fmaxf(mx0, fmaxf(ss[i][0], ss[i][1]));
            mx1 = fmaxf(mx1, fmaxf(ss[i][2], ss[i][3]));
        }
        mx0 = fmaxf(mx0, __shfl_xor_sync(0xffffffffu, mx0, 1));
        mx0 = fmaxf(mx0, __shfl_xor_sync(0xffffffffu, mx0, 2));
        mx1 = fmaxf(mx1, __shfl_xor_sync(0xffffffffu, mx1, 1));
        mx1 = fmaxf(mx1, __shfl_xor_sync(0xffffffffu, mx1, 2));

        float mn0 = fmaxf(m0, mx0), mn1 = fmaxf(m1, mx1);
        float al0 = __expf(m0 - mn0), al1 = __expf(m1 - mn1);
        float sum0 = 0.f, sum1 = 0.f;
#pragma unroll
        for (int i = 0; i < 16; i++) {
            ss[i][0] = __expf(ss[i][0] - mn0); sum0 += ss[i][0];
            ss[i][1] = __expf(ss[i][1] - mn0); sum0 += ss[i][1];
            ss[i][2] = __expf(ss[i][2] - mn1); sum1 += ss[i][2];
            ss[i][3] = __expf(ss[i][3] - mn1); sum1 += ss[i][3];
        }
        sum0 += __shfl_xor_sync(0xffffffffu, sum0, 1);
        sum0 += __shfl_xor_sync(0xffffffffu, sum0, 2);
        sum1 += __shfl_xor_sync(0xffffffffu, sum1, 1);
        sum1 += __shfl_xor_sync(0xffffffffu, sum1, 2);
        l0 = l0 * al0 + sum0;
        l1 = l1 * al1 + sum1;
        m0 = mn0; m1 = mn1;
#pragma unroll
        for (int v = 0; v < 8; v++) {
            o[v][0] *= al0; o[v][1] *= al0;
            o[v][2] *= al1; o[v][3] *= al1;
        }

#pragma unroll
        for (int ks = 0; ks < 8; ks++) {
            uint32_t ahi[4], alo[4];
            ahi[0] = pack2(ss[2 * ks][0], ss[2 * ks][1]);
            ahi[1] = pack2(ss[2 * ks][2], ss[2 * ks][3]);
            ahi[2] = pack2(ss[2 * ks + 1][0], ss[2 * ks + 1][1]);
            ahi[3] = pack2(ss[2 * ks + 1][2], ss[2 * ks + 1][3]);
            alo[0] = packlo2(ss[2 * ks][0], ss[2 * ks][1]);
            alo[1] = packlo2(ss[2 * ks][2], ss[2 * ks][3]);
            alo[2] = packlo2(ss[2 * ks + 1][0], ss[2 * ks + 1][1]);
            alo[3] = packlo2(ss[2 * ks + 1][2], ss[2 * ks + 1][3]);
#pragma unroll
            for (int nvp = 0; nvp < 4; nvp++) {
                uint32_t bv[4], bvl[4];
                uint32_t boff = ((nvp * 16 + ((lane >> 4) << 3) + (lane & 7)) * KSV
                                 + ks * 16 + (((lane >> 3) & 1) << 3)) * 2;
                ldm4(bv, uVh + boff);
                ldm4(bvl, uVl + boff);
                int nv = nvp * 2;
                mma16816(o[nv], ahi, bv);     mma16816(o[nv + 1], ahi, bv + 2);
                mma16816(o[nv], alo, bv);     mma16816(o[nv + 1], alo, bv + 2);
                mma16816(o[nv], ahi, bvl);    mma16816(o[nv + 1], ahi, bvl + 2);
            }
        }
    }

    float inv0 = 1.f / l0, inv1 = 1.f / l1;
    int row0 = qi * 128 + wq * 16 + fr;
#pragma unroll
    for (int v = 0; v < 8; v++) {
#pragma unroll
        for (int r = 0; r < 4; r++) {
            int row = row0 + ((r >> 1) << 3);
            int col = h * HDIM + v * 8 + fc * 2 + (r & 1);
            float val = o[v][r] * ((r >> 1) ? inv1 : inv0);
            long gi = (long)(b * NSEQ + row) * DMODEL + col;
            bf16 hh = __float2bfloat16(val);
            attnh[gi] = hh;
            attnl[gi] = __float2bfloat16(val - __bfloat162float(hh));
        }
    }
}

// ---------------------------------------------------------------------------
// Tensor-core GEMM template.
//   NMMA=3: bf16 hi/lo 3-term fp32 emulation (Ah/Al, Bh/Bl used).
//   NMMA=1: fp16 single-term (Ah, Bh only; Al/Bl ignored; half smem).
//   A: [M,K] 16-bit, stride lda.  B: [N,K] 16-bit, stride ldb.
//   128x128 tile, BK=32, 8 warps (2m x 4n), cp.async double-buffered,
//   ldmatrix fragment loads. flags: 1=residual, 2=exact GELU,
//   8=write fp32 C, 16=write bf16 hi/lo (NMMA=3 callers only).
// ---------------------------------------------------------------------------
template<int NMMA>
__global__ __launch_bounds__(256, 2) void bgemm_kernel(
    const uint16_t* __restrict__ Ah, const uint16_t* __restrict__ Al, int lda,
    const uint16_t* __restrict__ Bh, const uint16_t* __restrict__ Bl, int ldb,
    float* __restrict__ C, bf16* __restrict__ Ch, bf16* __restrict__ Cl, int ldc,
    const float* __restrict__ bias,
    int M, int N, int K, int flags) {

    constexpr int TPS = (NMMA == 3) ? 4 : 2;             // tiles per stage
    constexpr int BH_OFF = (NMMA == 3) ? 2 * TILE_E : TILE_E;

    int m0 = blockIdx.y * 128, n0 = blockIdx.x * 128;

    extern __shared__ uint16_t S[];
    uint32_t sbase = (uint32_t)__cvta_generic_to_shared(S);

    int tid = threadIdx.x, lane = tid & 31, wid = tid >> 5;
    int wm = wid & 1, wn = wid >> 1;
    int fr = lane >> 2, fc = lane & 3;

    int r2 = tid >> 1;
    int c2 = (tid & 1) * 16;

    float acc[4][4][4];
#pragma unroll
    for (int i = 0; i < 4; i++)
#pragma unroll
        for (int j = 0; j < 4; j++)
#pragma unroll
            for (int r = 0; r < 4; r++) acc[i][j][r] = 0.f;

    auto ldStage = [&](int k0, int bufi) {
        uint32_t sb = sbase + bufi * (TPS * TILE_E * 2);
        uint32_t sa = sb + r2 * (KS * 2) + c2 * 2;
        const uint16_t* ga = Ah + (long)(m0 + r2) * lda + k0 + c2;
        cp16(sa, ga);            cp16(sa + 16, ga + 8);
        if (NMMA == 3) {
            ga = Al + (long)(m0 + r2) * lda + k0 + c2;
            cp16(sa + TILE_E * 2, ga); cp16(sa + TILE_E * 2 + 16, ga + 8);
        }
        int gn = n0 + r2;
        uint32_t sbB = sb + BH_OFF * 2 + r2 * (KS * 2) + c2 * 2;
        if (gn < N) {
            const uint16_t* gb = Bh + (long)gn * ldb + k0 + c2;
            cp16(sbB, gb);            cp16(sbB + 16, gb + 8);
            if (NMMA == 3) {
                gb = Bl + (long)gn * ldb + k0 + c2;
                cp16(sbB + TILE_E * 2, gb); cp16(sbB + TILE_E * 2 + 16, gb + 8);
            }
        } else {
            uint4 zz = make_uint4(0, 0, 0, 0);
            uint16_t* p = S + bufi * TPS * TILE_E + BH_OFF + r2 * KS + c2;
            *(uint4*)p = zz; *(uint4*)(p + 8) = zz;
            if (NMMA == 3) {
                p += TILE_E;
                *(uint4*)p = zz; *(uint4*)(p + 8) = zz;
            }
        }
        asm volatile("cp.async.commit_group;\n" ::: "memory");
    };

    ldStage(0, 0);

    // per-thread ldmatrix address components (elem offsets)
    int aRow = wm * 64 + (lane & 15);
    int aColX = (lane >> 4) << 3;
    int bRow = wn * 32 + ((lane >> 4) << 3) + (lane & 7);
    int bColX = ((lane >> 3) & 1) << 3;

    int KT = K >> 5;
    int buf = 0;
    for (int kt = 0; kt < KT; kt++) {
        asm volatile("cp.async.wait_group 0;\n" ::: "memory");
        __syncthreads();
        if (kt + 1 < KT) ldStage((kt + 1) << 5, buf ^ 1);

        uint32_t sb = sbase + buf * (TPS * TILE_E * 2);

#pragma unroll
        for (int ks = 0; ks < 32; ks += 16) {
            uint32_t ah[4][4], bh[4][2];
            uint32_t aA = sb + (aRow * KS + ks + aColX) * 2;
            uint32_t bB = sb + BH_OFF * 2 + (bRow * KS + ks + bColX) * 2;
#pragma unroll
            for (int mi = 0; mi < 4; mi++) ldm4(ah[mi], aA + mi * (16 * KS * 2));
#pragma unroll
            for (int nip = 0; nip < 2; nip++)
                ldm4(&bh[nip * 2][0], bB + nip * (16 * KS * 2));

            if (NMMA == 3) {
                uint32_t al[4][4], bl[4][2];
#pragma unroll
                for (int mi = 0; mi < 4; mi++)
                    ldm4(al[mi], aA + mi * (16 * KS * 2) + TILE_E * 2);
#pragma unroll
                for (int nip = 0; nip < 2; nip++)
                    ldm4(&bl[nip * 2][0], bB + nip * (16 * KS * 2) + TILE_E * 2);
#pragma unroll
                for (int mi = 0; mi < 4; mi++)
#pragma unroll
                    for (int ni = 0; ni < 4; ni++)
                        mma16816(acc[mi][ni], ah[mi], bh[ni]);
#pragma unroll
                for (int mi = 0; mi < 4; mi++)
#pragma unroll
                    for (int ni = 0; ni < 4; ni++)
                        mma16816(acc[mi][ni], al[mi], bh[ni]);
#pragma unroll
                for (int ni = 0; ni < 4; ni++)
#pragma unroll
                    for (int mi = 0; mi < 4; mi++)
                        mma16816(acc[mi][ni], ah[mi], bl[ni]);
            } else {
#pragma unroll
                for (int mi = 0; mi < 4; mi++)
#pragma unroll
                    for (int ni = 0; ni < 4; ni++)
                        mma16816h(acc[mi][ni], ah[mi], bh[ni]);
            }
        }
        __syncthreads();
        buf ^= 1;
    }

    // Epilogue
#pragma unroll
    for (int mi = 0; mi < 4; mi++) {
        int gm0 = m0 + wm * 64 + mi * 16 + fr;
#pragma unroll
        for (int ni = 0; ni < 4; ni++) {
            int gn = n0 + wn * 32 + ni * 8 + fc * 2;
#pragma unroll
            for (int r = 0; r < 4; r++) {
                int gm = gm0 + (r >= 2 ? 8 : 0);
                int gc = gn + (r & 1);
                if (gc < N) {
                    float v = acc[mi][ni][r];
                    if (bias) v += bias[gc];
                    if (flags & 2) v = 0.5f * v * (1.f + erff(v * 0.70710678118654752f));
                    long idx = (long)gm * ldc + gc;
                    if (flags & 1) v += C[idx];
                    if (flags & 8) C[idx] = v;
                    if (flags & 16) {
                        bf16 h = __float2bfloat16(v);
                        Ch[idx] = h;
                        Cl[idx] = __float2bfloat16(v - __bfloat162float(h));
                    }
                }
            }
        }
    }
}

// ---------------------------------------------------------------------------
// Host-side orchestration
// ---------------------------------------------------------------------------
extern "C" void kernel_launch(void* const* d_in, const int* in_sizes, int n_in,
                              void* d_out, int out_size) {
    (void)in_sizes; (void)n_in; (void)out_size;

    const int*   tok     = (const int*)  d_in[0];
    const float* wte     = (const float*)d_in[1];
    const float* wpe     = (const float*)d_in[2];
    const float* ln1_w   = (const float*)d_in[3];
    const float* ln1_b   = (const float*)d_in[4];
    const float* attn_w  = (const float*)d_in[5];
    const float* attn_b  = (const float*)d_in[6];
    const float* aproj_w = (const float*)d_in[7];
    const float* aproj_b = (const float*)d_in[8];
    const float* ln2_w   = (const float*)d_in[9];
    const float* ln2_b   = (const float*)d_in[10];
    const float* fc_w    = (const float*)d_in[11];
    const float* fc_b    = (const float*)d_in[12];
    const float* mproj_w = (const float*)d_in[13];
    const float* mproj_b = (const float*)d_in[14];
    const float* lnf_w   = (const float*)d_in[15];
    const float* lnf_b   = (const float*)d_in[16];
    float* out = (float*)d_out;

    float *x;
    bf16 *lnh, *lnl, *qkvh, *qkvl, *attnh, *attnl, *midh, *midl;
    bf16 *wqkvh, *wqkvl, *waph, *wapl, *wfch, *wfcl, *wmph, *wmpl;
    __half *wtef, *lnf16;
    cudaGetSymbolAddress((void**)&x,      g_x);
    cudaGetSymbolAddress((void**)&lnh,    g_lnh);
    cudaGetSymbolAddress((void**)&lnl,    g_lnl);
    cudaGetSymbolAddress((void**)&qkvh,   g_qkvh);
    cudaGetSymbolAddress((void**)&qkvl,   g_qkvl);
    cudaGetSymbolAddress((void**)&attnh,  g_attnh);
    cudaGetSymbolAddress((void**)&attnl,  g_attnl);
    cudaGetSymbolAddress((void**)&midh,   g_midh);
    cudaGetSymbolAddress((void**)&midl,   g_midl);
    cudaGetSymbolAddress((void**)&wqkvh,  g_wqkvh);
    cudaGetSymbolAddress((void**)&wqkvl,  g_wqkvl);
    cudaGetSymbolAddress((void**)&waph,   g_waph);
    cudaGetSymbolAddress((void**)&wapl,   g_wapl);
    cudaGetSymbolAddress((void**)&wfch,   g_wfch);
    cudaGetSymbolAddress((void**)&wfcl,   g_wfcl);
    cudaGetSymbolAddress((void**)&wmph,   g_wmph);
    cudaGetSymbolAddress((void**)&wmpl,   g_wmpl);
    cudaGetSymbolAddress((void**)&wtef,   g_wtef);
    cudaGetSymbolAddress((void**)&lnf16,  g_lnf16);

    const int D = DMODEL;
    const int SMEM3 = 2 * 4 * TILE_E * 2;                              // 81920
    const int SMEM1 = 2 * 2 * TILE_E * 2;                              // 40960
    const int FSMEM = (4 * 128 * KSQ + 2 * 64 * KSV) * 2;              // 108544

    cudaFuncSetAttribute(bgemm_kernel<3>,
                         cudaFuncAttributeMaxDynamicSharedMemorySize, SMEM3);
    cudaFuncSetAttribute(bgemm_kernel<1>,
                         cudaFuncAttributeMaxDynamicSharedMemorySize, SMEM1);
    cudaFuncSetAttribute(flash_kernel,
                         cudaFuncAttributeMaxDynamicSharedMemorySize, FSMEM);

    // ---- weight prep (once per call) ----
    {
        dim3 b32(32, 8);
        tsplit_kernel<<<dim3(D / 32, 3 * D / 32, NLAYER), b32>>>(attn_w,  wqkvh, wqkvl, D, 3 * D);
        tsplit_kernel<<<dim3(D / 32, D / 32, NLAYER),     b32>>>(aproj_w, waph,  wapl,  D, D);
        tsplit_kernel<<<dim3(D / 32, 4 * D / 32, NLAYER), b32>>>(fc_w,    wfch,  wfcl,  D, 4 * D);
        tsplit_kernel<<<dim3(4 * D / 32, D / 32, NLAYER), b32>>>(mproj_w, wmph,  wmpl,  4 * D, D);
        long nwte = (long)NVOCAB * D;
        splitf16_kernel<<<(unsigned)((nwte + 255) / 256), 256>>>(wte, wtef, nwte);
    }

    embed_kernel<<<NTOK, 256>>>(tok, wte, wpe, x);

    for (int l = 0; l < NLAYER; l++) {
        layernorm_kernel<<<NTOK, 256>>>(x, ln1_w + l * D, ln1_b + l * D, lnh, lnl);

        // qkv = h @ attn_w[l] + attn_b[l] -> bf16 hi/lo
        {
            dim3 g(3 * D / 128, NTOK / 128);
            bgemm_kernel<3><<<g, 256, SMEM3>>>(
                (const uint16_t*)lnh, (const uint16_t*)lnl, D,
                (const uint16_t*)(wqkvh + (long)l * 3 * D * D),
                (const uint16_t*)(wqkvl + (long)l * 3 * D * D), D,
                nullptr, qkvh, qkvl, 3 * D,
                attn_b + (long)l * 3 * D,
                NTOK, 3 * D, D, 16);
        }

        // fused flash attention -> attnh/attnl
        flash_kernel<<<dim3(NSEQ / 128, 2 * NHEAD), 256, FSMEM>>>(qkvh, qkvl, attnh, attnl);

        // x += attn @ aproj_w[l] + aproj_b[l]
        {
            dim3 g(D / 128, NTOK / 128);
            bgemm_kernel<3><<<g, 256, SMEM3>>>(
                (const uint16_t*)attnh, (const uint16_t*)attnl, D,
                (const uint16_t*)(waph + (long)l * D * D),
                (const uint16_t*)(wapl + (long)l * D * D), D,
                x, nullptr, nullptr, D,
                aproj_b + (long)l * D,
                NTOK, D, D, 1 | 8);
        }

        layernorm_kernel<<<NTOK, 256>>>(x, ln2_w + l * D, ln2_b + l * D, lnh, lnl);

        // mid = gelu(h @ fc_w[l] + fc_b[l]) -> hi/lo
        {
            dim3 g(4 * D / 128, NTOK / 128);
            bgemm_kernel<3><<<g, 256, SMEM3>>>(
                (const uint16_t*)lnh, (const uint16_t*)lnl, D,
                (const uint16_t*)(wfch + (long)l * 4 * D * D),
                (const uint16_t*)(wfcl + (long)l * 4 * D * D), D,
                nullptr, midh, midl, 4 * D,
                fc_b + (long)l * 4 * D,
                NTOK, 4 * D, D, 2 | 16);
        }

        // x += mid @ mproj_w[l] + mproj_b[l]
        {
            dim3 g(D / 128, NTOK / 128);
            bgemm_kernel<3><<<g, 256, SMEM3>>>(
                (const uint16_t*)midh, (const uint16_t*)midl, 4 * D,
                (const uint16_t*)(wmph + (long)l * D * 4 * D),
                (const uint16_t*)(wmpl + (long)l * D * 4 * D), 4 * D,
                x, nullptr, nullptr, D,
                mproj_b + (long)l * D,
                NTOK, D, 4 * D, 1 | 8);
        }
    }

    // final LN (fp16) + tied lm_head in single-term fp16: out = LN_f(x) @ wte^T
    layernorm_f16_kernel<<<NTOK, 256>>>(x, lnf_w, lnf_b, lnf16);
    {
        dim3 g((NVOCAB + 127) / 128, NTOK / 128);
        bgemm_kernel<1><<<g, 256, SMEM1>>>(
            (const uint16_t*)lnf16, nullptr, D,
            (const uint16_t*)wtef, nullptr, D,
            out, nullptr, nullptr, NVOCAB,
            nullptr,
            NTOK, NVOCAB, D, 8);
    }
}

// round 9
// speedup vs baseline: 4.5654x; 1.2390x over previous
#include <cuda_runtime.h>
#include <cuda_bf16.h>
#include <cuda_fp16.h>
#include <math.h>
#include <stdint.h>

// Problem constants
#define DMODEL 768
#define NTOK   2048          // B*N = 2*1024
#define NSEQ   1024
#define NHEAD  12
#define HDIM   64
#define NLAYER 12
#define NVOCAB 50257

#define KS 40                 // gemm smem k-stride in 16-bit elems (conflict-free)
#define TILE_E (128 * KS)     // elems per smem tile array
#define KSQ 72                // flash Q/K smem stride (64+8)
#define KSV 136               // flash V^T smem stride (128+8)

typedef __half f16;

// ---------------------------------------------------------------------------
// Device-global scratch (allocation-free)
// ---------------------------------------------------------------------------
__device__ float g_x[NTOK * DMODEL];                  // residual stream (fp32)

// activations, fp16 hi/lo
__device__ f16 g_lnh[NTOK * DMODEL],      g_lnl[NTOK * DMODEL];
__device__ f16 g_qkvh[NTOK * 3 * DMODEL], g_qkvl[NTOK * 3 * DMODEL];
__device__ f16 g_attnh[NTOK * DMODEL],    g_attnl[NTOK * DMODEL];
__device__ f16 g_midh[NTOK * 4 * DMODEL], g_midl[NTOK * 4 * DMODEL];

// final-LN output in fp16 (lm_head only)
__device__ f16 g_lnf16[NTOK * DMODEL];

// weights, transposed to [N,K], fp16 hi/lo
__device__ f16 g_wqkvh[NLAYER * 3 * DMODEL * DMODEL], g_wqkvl[NLAYER * 3 * DMODEL * DMODEL];
__device__ f16 g_waph [NLAYER * DMODEL * DMODEL],     g_wapl [NLAYER * DMODEL * DMODEL];
__device__ f16 g_wfch [NLAYER * 4 * DMODEL * DMODEL], g_wfcl [NLAYER * 4 * DMODEL * DMODEL];
__device__ f16 g_wmph [NLAYER * DMODEL * 4 * DMODEL], g_wmpl [NLAYER * DMODEL * 4 * DMODEL];
__device__ f16 g_wtef[(long)NVOCAB * DMODEL];         // wte in fp16 (lm_head)

// ---------------------------------------------------------------------------
// Helpers
// ---------------------------------------------------------------------------
__device__ __forceinline__ float blockReduceSum(float v) {
    __shared__ float sh[8];
    int lane = threadIdx.x & 31, w = threadIdx.x >> 5;
#pragma unroll
    for (int o = 16; o; o >>= 1) v += __shfl_xor_sync(0xffffffffu, v, o);
    __syncthreads();
    if (lane == 0) sh[w] = v;
    __syncthreads();
    if (threadIdx.x == 0) {
        float s = sh[0];
#pragma unroll
        for (int i = 1; i < 8; i++) s += sh[i];
        sh[0] = s;
    }
    __syncthreads();
    return sh[0];
}

__device__ __forceinline__ void cp16(uint32_t saddr, const void* gaddr) {
    asm volatile("cp.async.cg.shared.global [%0], [%1], 16;\n"
                 :: "r"(saddr), "l"(gaddr));
}

__device__ __forceinline__ void mma16816h(float* d, const uint32_t* a, const uint32_t* b) {
    asm volatile(
        "mma.sync.aligned.m16n8k16.row.col.f32.f16.f16.f32 "
        "{%0,%1,%2,%3},{%4,%5,%6,%7},{%8,%9},{%0,%1,%2,%3};\n"
        : "+f"(d[0]), "+f"(d[1]), "+f"(d[2]), "+f"(d[3])
        : "r"(a[0]), "r"(a[1]), "r"(a[2]), "r"(a[3]), "r"(b[0]), "r"(b[1]));
}

__device__ __forceinline__ void ldm4(uint32_t* r, uint32_t addr) {
    asm volatile("ldmatrix.sync.aligned.m8n8.x4.shared.b16 {%0,%1,%2,%3}, [%4];\n"
                 : "=r"(r[0]), "=r"(r[1]), "=r"(r[2]), "=r"(r[3]) : "r"(addr));
}

__device__ __forceinline__ uint32_t pack2h(float a, float b) {
    __half2 t = __floats2half2_rn(a, b);
    return *(uint32_t*)&t;
}
__device__ __forceinline__ uint32_t packlo2h(float a, float b) {
    float la = a - __half2float(__float2half(a));
    float lb = b - __half2float(__float2half(b));
    return pack2h(la, lb);
}

// ---------------------------------------------------------------------------
// Weight prep: transpose+split W[z][K][N] -> T[z][N][K] hi/lo fp16
// ---------------------------------------------------------------------------
__global__ void tsplit_kernel(const float* __restrict__ W,
                              f16* __restrict__ Th, f16* __restrict__ Tl,
                              int K, int N) {
    __shared__ float t[32][33];
    long zoff = (long)blockIdx.z * K * N;
    W += zoff; Th += zoff; Tl += zoff;
    int k0 = blockIdx.x * 32, n0 = blockIdx.y * 32;
    int tx = threadIdx.x, ty = threadIdx.y;
#pragma unroll
    for (int i = 0; i < 4; i++)
        t[ty + i * 8][tx] = W[(long)(k0 + ty + i * 8) * N + n0 + tx];
    __syncthreads();
#pragma unroll
    for (int i = 0; i < 4; i++) {
        int n = n0 + ty + i * 8, k = k0 + tx;
        float v = t[tx][ty + i * 8];
        f16 h = __float2half(v);
        Th[(long)n * K + k] = h;
        Tl[(long)n * K + k] = __float2half(v - __half2float(h));
    }
}

// Elementwise fp32 -> fp16 (wte is already [V, D] = [N, K])
__global__ void splitf16_kernel(const float* __restrict__ in,
                                f16* __restrict__ o, long n) {
    long i = (long)blockIdx.x * 256 + threadIdx.x;
    if (i < n) o[i] = __float2half(in[i]);
}

// ---------------------------------------------------------------------------
// Embedding
// ---------------------------------------------------------------------------
__global__ void embed_kernel(const int* __restrict__ tok,
                             const float* __restrict__ wte,
                             const float* __restrict__ wpe,
                             float* __restrict__ x) {
    int t = blockIdx.x;
    int n = t & (NSEQ - 1);
    int id = tok[t];
    const float* w1 = wte + (long)id * DMODEL;
    const float* w2 = wpe + (long)n * DMODEL;
    float* xo = x + (long)t * DMODEL;
    for (int d = threadIdx.x; d < DMODEL; d += blockDim.x)
        xo[d] = w1[d] + w2[d];
}

// ---------------------------------------------------------------------------
// LayerNorm: fp32 in -> fp16 hi/lo out
// ---------------------------------------------------------------------------
__global__ __launch_bounds__(256) void layernorm_kernel(
    const float* __restrict__ x, const float* __restrict__ w,
    const float* __restrict__ b,
    f16* __restrict__ oh, f16* __restrict__ ol) {
    int t = blockIdx.x;
    const float* xr = x + (long)t * DMODEL;
    int tid = threadIdx.x;

    float lx[3];
    float s = 0.f;
#pragma unroll
    for (int i = 0; i < 3; i++) { lx[i] = xr[tid + i * 256]; s += lx[i]; }
    s = blockReduceSum(s);
    float mu = s * (1.f / 768.f);

    float var = 0.f;
#pragma unroll
    for (int i = 0; i < 3; i++) { float d = lx[i] - mu; var += d * d; }
    var = blockReduceSum(var);
    float rstd = rsqrtf(var * (1.f / 768.f) + 1e-5f);

#pragma unroll
    for (int i = 0; i < 3; i++) {
        int d = tid + i * 256;
        float v = (lx[i] - mu) * rstd * w[d] + b[d];
        f16 h = __float2half(v);
        oh[(long)t * DMODEL + d] = h;
        ol[(long)t * DMODEL + d] = __float2half(v - __half2float(h));
    }
}

// LayerNorm: fp32 in -> fp16 out (final LN, feeds fp16 lm_head)
__global__ __launch_bounds__(256) void layernorm_f16_kernel(
    const float* __restrict__ x, const float* __restrict__ w,
    const float* __restrict__ b, f16* __restrict__ o) {
    int t = blockIdx.x;
    const float* xr = x + (long)t * DMODEL;
    int tid = threadIdx.x;

    float lx[3];
    float s = 0.f;
#pragma unroll
    for (int i = 0; i < 3; i++) { lx[i] = xr[tid + i * 256]; s += lx[i]; }
    s = blockReduceSum(s);
    float mu = s * (1.f / 768.f);

    float var = 0.f;
#pragma unroll
    for (int i = 0; i < 3; i++) { float d = lx[i] - mu; var += d * d; }
    var = blockReduceSum(var);
    float rstd = rsqrtf(var * (1.f / 768.f) + 1e-5f);

#pragma unroll
    for (int i = 0; i < 3; i++) {
        int d = tid + i * 256;
        float v = (lx[i] - mu) * rstd * w[d] + b[d];
        o[(long)t * DMODEL + d] = __float2half(v);
    }
}

// ---------------------------------------------------------------------------
// Flash attention, fp16 2-term: S = Qh.Kh + Ql.Kh ; O += Ph.Vh + Pl.Vh.
// One block per (q-tile of 128 rows, head z); 8 warps, 16 q-rows each.
// Smem: Qh, Ql, Kh [128*KSQ each] + VTh [64*KSV].
// ---------------------------------------------------------------------------
__global__ __launch_bounds__(256) void flash_kernel(
    const f16* __restrict__ qkvh, const f16* __restrict__ qkvl,
    f16* __restrict__ attnh, f16* __restrict__ attnl) {

    int qi = blockIdx.x;
    int z = blockIdx.y;
    int b = z / NHEAD, h = z - b * NHEAD;
    const int rs = 3 * DMODEL;
    long base = (long)b * NSEQ * rs + h * HDIM;

    extern __shared__ f16 SM[];
    uint32_t u0 = (uint32_t)__cvta_generic_to_shared(SM);
    const uint32_t uQh = u0;
    const uint32_t uQl = uQh + 128 * KSQ * 2;
    const uint32_t uKh = uQl + 128 * KSQ * 2;
    const uint32_t uVh = uKh + 128 * KSQ * 2;
    f16* sVh = SM + 3 * 128 * KSQ;

    int tid = threadIdx.x, lane = tid & 31, wq = tid >> 5;
    int fr = lane >> 2, fc = lane & 3;

    // ---- load Q tile (cp.async, hi/lo) ----
    {
        int r = tid >> 1, c0 = (tid & 1) * 32;
        const f16* g = qkvh + base + (long)(qi * 128 + r) * rs + c0;
        uint32_t s = uQh + (r * KSQ + c0) * 2;
        cp16(s, g); cp16(s + 16, g + 8); cp16(s + 32, g + 16); cp16(s + 48, g + 24);
        g = qkvl + base + (long)(qi * 128 + r) * rs + c0;
        s = uQl + (r * KSQ + c0) * 2;
        cp16(s, g); cp16(s + 16, g + 8); cp16(s + 32, g + 16); cp16(s + 48, g + 24);
        asm volatile("cp.async.commit_group;\n" ::: "memory");
    }

    float m0 = -1e30f, m1 = -1e30f, l0 = 0.f, l1 = 0.f;
    float o[8][4] = {};

    for (int kt = 0; kt <= qi; kt++) {
        __syncthreads();

        // ---- load K tile hi (cp.async) ----
        {
            int r = tid >> 1, c0 = (tid & 1) * 32;
            const f16* g = qkvh + base + DMODEL + (long)(kt * 128 + r) * rs + c0;
            uint32_t s = uKh + (r * KSQ + c0) * 2;
            cp16(s, g); cp16(s + 16, g + 8); cp16(s + 32, g + 16); cp16(s + 48, g + 24);
            asm volatile("cp.async.commit_group;\n" ::: "memory");
        }
        // ---- load V^T hi (sync transposed scatter) ----
        {
            int t = tid >> 1, c0 = (tid & 1) * 32;
            const f16* g = qkvh + base + 2 * DMODEL + (long)(kt * 128 + t) * rs + c0;
            union { uint4 u[4]; f16 e[32]; } vb;
            vb.u[0] = ((const uint4*)g)[0]; vb.u[1] = ((const uint4*)g)[1];
            vb.u[2] = ((const uint4*)g)[2]; vb.u[3] = ((const uint4*)g)[3];
#pragma unroll
            for (int j = 0; j < 32; j++) sVh[(c0 + j) * KSV + t] = vb.e[j];
        }
        asm volatile("cp.async.wait_group 0;\n" ::: "memory");
        __syncthreads();

        // ---- S = Q @ K^T (2-term fp16) ----
        float ss[16][4];
#pragma unroll
        for (int i = 0; i < 16; i++)
#pragma unroll
            for (int r = 0; r < 4; r++) ss[i][r] = 0.f;

#pragma unroll
        for (int ks4 = 0; ks4 < 4; ks4++) {
            int ks = ks4 * 16;
            uint32_t ah[4], al[4];
            uint32_t aoff = ((wq * 16 + (lane & 15)) * KSQ + ks + ((lane >> 4) << 3)) * 2;
            ldm4(ah, uQh + aoff);
            ldm4(al, uQl + aoff);
#pragma unroll
            for (int nip = 0; nip < 8; nip++) {
                uint32_t bh[4];
                uint32_t boff = ((nip * 16 + ((lane >> 4) << 3) + (lane & 7)) * KSQ
                                 + ks + (((lane >> 3) & 1) << 3)) * 2;
                ldm4(bh, uKh + boff);
                int ni = nip * 2;
                mma16816h(ss[ni], ah, bh);     mma16816h(ss[ni + 1], ah, bh + 2);
                mma16816h(ss[ni], al, bh);     mma16816h(ss[ni + 1], al, bh + 2);
            }
        }

        // ---- scale + causal mask ----
#pragma unroll
        for (int i = 0; i < 16; i++)
#pragma unroll
            for (int r = 0; r < 4; r++) ss[i][r] *= 0.125f;
        if (kt == qi) {
#pragma unroll
            for (int i = 0; i < 16; i++)
#pragma unroll
                for (int r = 0; r < 4; r++) {
                    int col = i * 8 + fc * 2 + (r & 1);
                    int row = wq * 16 + fr + ((r >> 1) << 3);
                    if (col > row) ss[i][r] = -1e30f;
                }
        }

        // ---- online softmax ----
        float mx0 = -1e30f, mx1 = -1e30f;
#pragma unroll
        for (int i = 0; i < 16; i++) {
            mx0 = fmaxf(mx0, fmaxf(ss[i][0], ss[i][1]));
            mx1 = fmaxf(mx1, fmaxf(ss[i][2], ss[i][3]));
        }
        mx0 = fmaxf(mx0, __shfl_xor_sync(0xffffffffu, mx0, 1));
        mx0 = fmaxf(mx0, __shfl_xor_sync(0xffffffffu, mx0, 2));
        mx1 = fmaxf(mx1, __shfl_xor_sync(0xffffffffu, mx1, 1));
        mx1 = fmaxf(mx1, __shfl_xor_sync(0xffffffffu, mx1, 2));

        float mn0 = fmaxf(m0, mx0), mn1 = fmaxf(m1, mx1);
        float al0 = __expf(m0 - mn0), al1 = __expf(m1 - mn1);
        float sum0 = 0.f, sum1 = 0.f;
#pragma unroll
        for (int i = 0; i < 16; i++) {
            ss[i][0] = __expf(ss[i][0] - mn0); sum0 += ss[i][0];
            ss[i][1] = __expf(ss[i][1] - mn0); sum0 += ss[i][1];
            ss[i][2] = __expf(ss[i][2] - mn1); sum1 += ss[i][2];
            ss[i][3] = __expf(ss[i][3] - mn1); sum1 += ss[i][3];
        }
        sum0 += __shfl_xor_sync(0xffffffffu, sum0, 1);
        sum0 += __shfl_xor_sync(0xffffffffu, sum0, 2);
        sum1 += __shfl_xor_sync(0xffffffffu, sum1, 1);
        sum1 += __shfl_xor_sync(0xffffffffu, sum1, 2);
        l0 = l0 * al0 + sum0;
        l1 = l1 * al1 + sum1;
        m0 = mn0; m1 = mn1;
#pragma unroll
        for (int v = 0; v < 8; v++) {
            o[v][0] *= al0; o[v][1] *= al0;
            o[v][2] *= al1; o[v][3] *= al1;
        }

        // ---- O += P @ V (P hi/lo fp16 from regs, V^T hi from smem) ----
#pragma unroll
        for (int ks = 0; ks < 8; ks++) {
            uint32_t ahi[4], alo[4];
            ahi[0] = pack2h(ss[2 * ks][0], ss[2 * ks][1]);
            ahi[1] = pack2h(ss[2 * ks][2], ss[2 * ks][3]);
            ahi[2] = pack2h(ss[2 * ks + 1][0], ss[2 * ks + 1][1]);
            ahi[3] = pack2h(ss[2 * ks + 1][2], ss[2 * ks + 1][3]);
            alo[0] = packlo2h(ss[2 * ks][0], ss[2 * ks][1]);
            alo[1] = packlo2h(ss[2 * ks][2], ss[2 * ks][3]);
            alo[2] = packlo2h(ss[2 * ks + 1][0], ss[2 * ks + 1][1]);
            alo[3] = packlo2h(ss[2 * ks + 1][2], ss[2 * ks + 1][3]);
#pragma unroll
            for (int nvp = 0; nvp < 4; nvp++) {
                uint32_t bv[4];
                uint32_t boff = ((nvp * 16 + ((lane >> 4) << 3) + (lane & 7)) * KSV
                                 + ks * 16 + (((lane >> 3) & 1) << 3)) * 2;
                ldm4(bv, uVh + boff);
                int nv = nvp * 2;
                mma16816h(o[nv], ahi, bv);     mma16816h(o[nv + 1], ahi, bv + 2);
                mma16816h(o[nv], alo, bv);     mma16816h(o[nv + 1], alo, bv + 2);
            }
        }
    }

    // ---- epilogue: O /= l, write fp16 hi/lo ----
    float inv0 = 1.f / l0, inv1 = 1.f / l1;
    int row0 = qi * 128 + wq * 16 + fr;
#pragma unroll
    for (int v = 0; v < 8; v++) {
#pragma unroll
        for (int r = 0; r < 4; r++) {
            int row = row0 + ((r >> 1) << 3);
            int col = h * HDIM + v * 8 + fc * 2 + (r & 1);
            float val = o[v][r] * ((r >> 1) ? inv1 : inv0);
            long gi = (long)(b * NSEQ + row) * DMODEL + col;
            f16 hh = __float2half(val);
            attnh[gi] = hh;
            attnl[gi] = __float2half(val - __half2float(hh));
        }
    }
}

// ---------------------------------------------------------------------------
// Tensor-core GEMM template (fp16).
//   NMMA=2: 2-term hi/lo (Ah/Al + Bh; acc = Ah.Bh + Al.Bh).
//   NMMA=1: single-term (Ah, Bh only).
//   A: [M,K], stride lda.  B: [N,K], stride ldb.
//   128x128 tile, BK=32, 8 warps (2m x 4n), cp.async double-buffered,
//   ldmatrix fragment loads. flags: 1=residual, 2=exact GELU,
//   8=write fp32 C, 16=write fp16 hi/lo (Ch, Cl).
// ---------------------------------------------------------------------------
template<int NMMA>
__global__ __launch_bounds__(256, 2) void bgemm_kernel(
    const uint16_t* __restrict__ Ah, const uint16_t* __restrict__ Al, int lda,
    const uint16_t* __restrict__ Bh, int ldb,
    float* __restrict__ C, f16* __restrict__ Ch, f16* __restrict__ Cl, int ldc,
    const float* __restrict__ bias,
    int M, int N, int K, int flags) {

    constexpr int TPS = (NMMA == 2) ? 3 : 2;             // tiles per stage
    constexpr int BH_OFF = (NMMA == 2) ? 2 * TILE_E : TILE_E;

    int m0 = blockIdx.y * 128, n0 = blockIdx.x * 128;

    extern __shared__ uint16_t S[];
    uint32_t sbase = (uint32_t)__cvta_generic_to_shared(S);

    int tid = threadIdx.x, lane = tid & 31, wid = tid >> 5;
    int wm = wid & 1, wn = wid >> 1;
    int fr = lane >> 2, fc = lane & 3;

    int r2 = tid >> 1;
    int c2 = (tid & 1) * 16;

    float acc[4][4][4];
#pragma unroll
    for (int i = 0; i < 4; i++)
#pragma unroll
        for (int j = 0; j < 4; j++)
#pragma unroll
            for (int r = 0; r < 4; r++) acc[i][j][r] = 0.f;

    auto ldStage = [&](int k0, int bufi) {
        uint32_t sb = sbase + bufi * (TPS * TILE_E * 2);
        uint32_t sa = sb + r2 * (KS * 2) + c2 * 2;
        const uint16_t* ga = Ah + (long)(m0 + r2) * lda + k0 + c2;
        cp16(sa, ga);            cp16(sa + 16, ga + 8);
        if (NMMA == 2) {
            ga = Al + (long)(m0 + r2) * lda + k0 + c2;
            cp16(sa + TILE_E * 2, ga); cp16(sa + TILE_E * 2 + 16, ga + 8);
        }
        int gn = n0 + r2;
        uint32_t sbB = sb + BH_OFF * 2 + r2 * (KS * 2) + c2 * 2;
        if (gn < N) {
            const uint16_t* gb = Bh + (long)gn * ldb + k0 + c2;
            cp16(sbB, gb);            cp16(sbB + 16, gb + 8);
        } else {
            uint4 zz = make_uint4(0, 0, 0, 0);
            uint16_t* p = S + bufi * TPS * TILE_E + BH_OFF + r2 * KS + c2;
            *(uint4*)p = zz; *(uint4*)(p + 8) = zz;
        }
        asm volatile("cp.async.commit_group;\n" ::: "memory");
    };

    ldStage(0, 0);

    // per-thread ldmatrix address components (elem offsets)
    int aRow = wm * 64 + (lane & 15);
    int aColX = (lane >> 4) << 3;
    int bRow = wn * 32 + ((lane >> 4) << 3) + (lane & 7);
    int bColX = ((lane >> 3) & 1) << 3;

    int KT = K >> 5;
    int buf = 0;
    for (int kt = 0; kt < KT; kt++) {
        asm volatile("cp.async.wait_group 0;\n" ::: "memory");
        __syncthreads();
        if (kt + 1 < KT) ldStage((kt + 1) << 5, buf ^ 1);

        uint32_t sb = sbase + buf * (TPS * TILE_E * 2);

#pragma unroll
        for (int ks = 0; ks < 32; ks += 16) {
            uint32_t ah[4][4], bh[4][2];
            uint32_t aA = sb + (aRow * KS + ks + aColX) * 2;
            uint32_t bB = sb + BH_OFF * 2 + (bRow * KS + ks + bColX) * 2;
#pragma unroll
            for (int mi = 0; mi < 4; mi++) ldm4(ah[mi], aA + mi * (16 * KS * 2));
#pragma unroll
            for (int nip = 0; nip < 2; nip++)
                ldm4(&bh[nip * 2][0], bB + nip * (16 * KS * 2));

#pragma unroll
            for (int mi = 0; mi < 4; mi++)
#pragma unroll
                for (int ni = 0; ni < 4; ni++)
                    mma16816h(acc[mi][ni], ah[mi], bh[ni]);

            if (NMMA == 2) {
                uint32_t al[4][4];
#pragma unroll
                for (int mi = 0; mi < 4; mi++)
                    ldm4(al[mi], aA + mi * (16 * KS * 2) + TILE_E * 2);
#pragma unroll
                for (int mi = 0; mi < 4; mi++)
#pragma unroll
                    for (int ni = 0; ni < 4; ni++)
                        mma16816h(acc[mi][ni], al[mi], bh[ni]);
            }
        }
        __syncthreads();
        buf ^= 1;
    }

    // Epilogue
#pragma unroll
    for (int mi = 0; mi < 4; mi++) {
        int gm0 = m0 + wm * 64 + mi * 16 + fr;
#pragma unroll
        for (int ni = 0; ni < 4; ni++) {
            int gn = n0 + wn * 32 + ni * 8 + fc * 2;
#pragma unroll
            for (int r = 0; r < 4; r++) {
                int gm = gm0 + (r >= 2 ? 8 : 0);
                int gc = gn + (r & 1);
                if (gc < N) {
                    float v = acc[mi][ni][r];
                    if (bias) v += bias[gc];
                    if (flags & 2) v = 0.5f * v * (1.f + erff(v * 0.70710678118654752f));
                    long idx = (long)gm * ldc + gc;
                    if (flags & 1) v += C[idx];
                    if (flags & 8) C[idx] = v;
                    if (flags & 16) {
                        f16 h = __float2half(v);
                        Ch[idx] = h;
                        Cl[idx] = __float2half(v - __half2float(h));
                    }
                }
            }
        }
    }
}

// ---------------------------------------------------------------------------
// Host-side orchestration
// ---------------------------------------------------------------------------
extern "C" void kernel_launch(void* const* d_in, const int* in_sizes, int n_in,
                              void* d_out, int out_size) {
    (void)in_sizes; (void)n_in; (void)out_size;

    const int*   tok     = (const int*)  d_in[0];
    const float* wte     = (const float*)d_in[1];
    const float* wpe     = (const float*)d_in[2];
    const float* ln1_w   = (const float*)d_in[3];
    const float* ln1_b   = (const float*)d_in[4];
    const float* attn_w  = (const float*)d_in[5];
    const float* attn_b  = (const float*)d_in[6];
    const float* aproj_w = (const float*)d_in[7];
    const float* aproj_b = (const float*)d_in[8];
    const float* ln2_w   = (const float*)d_in[9];
    const float* ln2_b   = (const float*)d_in[10];
    const float* fc_w    = (const float*)d_in[11];
    const float* fc_b    = (const float*)d_in[12];
    const float* mproj_w = (const float*)d_in[13];
    const float* mproj_b = (const float*)d_in[14];
    const float* lnf_w   = (const float*)d_in[15];
    const float* lnf_b   = (const float*)d_in[16];
    float* out = (float*)d_out;

    float *x;
    f16 *lnh, *lnl, *qkvh, *qkvl, *attnh, *attnl, *midh, *midl;
    f16 *wqkvh, *wqkvl, *waph, *wapl, *wfch, *wfcl, *wmph, *wmpl;
    f16 *wtef, *lnf16;
    cudaGetSymbolAddress((void**)&x,      g_x);
    cudaGetSymbolAddress((void**)&lnh,    g_lnh);
    cudaGetSymbolAddress((void**)&lnl,    g_lnl);
    cudaGetSymbolAddress((void**)&qkvh,   g_qkvh);
    cudaGetSymbolAddress((void**)&qkvl,   g_qkvl);
    cudaGetSymbolAddress((void**)&attnh,  g_attnh);
    cudaGetSymbolAddress((void**)&attnl,  g_attnl);
    cudaGetSymbolAddress((void**)&midh,   g_midh);
    cudaGetSymbolAddress((void**)&midl,   g_midl);
    cudaGetSymbolAddress((void**)&wqkvh,  g_wqkvh);
    cudaGetSymbolAddress((void**)&wqkvl,  g_wqkvl);
    cudaGetSymbolAddress((void**)&waph,   g_waph);
    cudaGetSymbolAddress((void**)&wapl,   g_wapl);
    cudaGetSymbolAddress((void**)&wfch,   g_wfch);
    cudaGetSymbolAddress((void**)&wfcl,   g_wfcl);
    cudaGetSymbolAddress((void**)&wmph,   g_wmph);
    cudaGetSymbolAddress((void**)&wmpl,   g_wmpl);
    cudaGetSymbolAddress((void**)&wtef,   g_wtef);
    cudaGetSymbolAddress((void**)&lnf16,  g_lnf16);

    const int D = DMODEL;
    const int SMEM2 = 2 * 3 * TILE_E * 2;                              // 61440
    const int SMEM1 = 2 * 2 * TILE_E * 2;                              // 40960
    const int FSMEM = (3 * 128 * KSQ + 64 * KSV) * 2;                  // 72704

    cudaFuncSetAttribute(bgemm_kernel<2>,
                         cudaFuncAttributeMaxDynamicSharedMemorySize, SMEM2);
    cudaFuncSetAttribute(bgemm_kernel<1>,
                         cudaFuncAttributeMaxDynamicSharedMemorySize, SMEM1);
    cudaFuncSetAttribute(flash_kernel,
                         cudaFuncAttributeMaxDynamicSharedMemorySize, FSMEM);

    // ---- weight prep (once per call) ----
    {
        dim3 b32(32, 8);
        tsplit_kernel<<<dim3(D / 32, 3 * D / 32, NLAYER), b32>>>(attn_w,  wqkvh, wqkvl, D, 3 * D);
        tsplit_kernel<<<dim3(D / 32, D / 32, NLAYER),     b32>>>(aproj_w, waph,  wapl,  D, D);
        tsplit_kernel<<<dim3(D / 32, 4 * D / 32, NLAYER), b32>>>(fc_w,    wfch,  wfcl,  D, 4 * D);
        tsplit_kernel<<<dim3(4 * D / 32, D / 32, NLAYER), b32>>>(mproj_w, wmph,  wmpl,  4 * D, D);
        long nwte = (long)NVOCAB * D;
        splitf16_kernel<<<(unsigned)((nwte + 255) / 256), 256>>>(wte, wtef, nwte);
    }

    embed_kernel<<<NTOK, 256>>>(tok, wte, wpe, x);

    for (int l = 0; l < NLAYER; l++) {
        layernorm_kernel<<<NTOK, 256>>>(x, ln1_w + l * D, ln1_b + l * D, lnh, lnl);

        // qkv = h @ attn_w[l] + attn_b[l] -> fp16 hi/lo
        {
            dim3 g(3 * D / 128, NTOK / 128);
            bgemm_kernel<2><<<g, 256, SMEM2>>>(
                (const uint16_t*)lnh, (const uint16_t*)lnl, D,
                (const uint16_t*)(wqkvh + (long)l * 3 * D * D), D,
                nullptr, qkvh, qkvl, 3 * D,
                attn_b + (long)l * 3 * D,
                NTOK, 3 * D, D, 16);
        }

        // fused flash attention -> attnh/attnl
        flash_kernel<<<dim3(NSEQ / 128, 2 * NHEAD), 256, FSMEM>>>(qkvh, qkvl, attnh, attnl);

        // x += attn @ aproj_w[l] + aproj_b[l]
        {
            dim3 g(D / 128, NTOK / 128);
            bgemm_kernel<2><<<g, 256, SMEM2>>>(
                (const uint16_t*)attnh, (const uint16_t*)attnl, D,
                (const uint16_t*)(waph + (long)l * D * D), D,
                x, nullptr, nullptr, D,
                aproj_b + (long)l * D,
                NTOK, D, D, 1 | 8);
        }

        layernorm_kernel<<<NTOK, 256>>>(x, ln2_w + l * D, ln2_b + l * D, lnh, lnl);

        // mid = gelu(h @ fc_w[l] + fc_b[l]) -> fp16 hi/lo
        {
            dim3 g(4 * D / 128, NTOK / 128);
            bgemm_kernel<2><<<g, 256, SMEM2>>>(
                (const uint16_t*)lnh, (const uint16_t*)lnl, D,
                (const uint16_t*)(wfch + (long)l * 4 * D * D), D,
                nullptr, midh, midl, 4 * D,
                fc_b + (long)l * 4 * D,
                NTOK, 4 * D, D, 2 | 16);
        }

        // x += mid @ mproj_w[l] + mproj_b[l]
        {
            dim3 g(D / 128, NTOK / 128);
            bgemm_kernel<2><<<g, 256, SMEM2>>>(
                (const uint16_t*)midh, (const uint16_t*)midl, 4 * D,
                (const uint16_t*)(wmph + (long)l * D * 4 * D), 4 * D,
                x, nullptr, nullptr, D,
                mproj_b + (long)l * D,
                NTOK, D, 4 * D, 1 | 8);
        }
    }

    // final LN (fp16) + tied lm_head in single-term fp16: out = LN_f(x) @ wte^T
    layernorm_f16_kernel<<<NTOK, 256>>>(x, lnf_w, lnf_b, lnf16);
    {
        dim3 g((NVOCAB + 127) / 128, NTOK / 128);
        bgemm_kernel<1><<<g, 256, SMEM1>>>(
            (const uint16_t*)lnf16, nullptr, D,
            (const uint16_t*)wtef, D,
            out, nullptr, nullptr, NVOCAB,
            nullptr,
            NTOK, NVOCAB, D, 8);
    }
}